// round 2
// baseline (speedup 1.0000x reference)
#include <cuda_runtime.h>

// Shapes (fixed for this problem)
#define B_ 128
#define C_ 1024
#define D_ 256                   // = T (timesteps) = hidden dim
#define ROWS (B_*C_)             // 131072 rows for mix branch
#define CB (C_*B_)               // 131072
#define OB (D_*B_)               // 32768

// ---------------- scratch (static __device__, no allocation) ----------------
__device__ float g_xn[ROWS*D_];          // layernormed x          128 MB
__device__ float g_h [ROWS*D_];          // mix hidden             128 MB
__device__ float g_s1[D_*C_*B_];         // spikes 1 [t,c,b]       128 MB
__device__ float g_y1[D_*D_*B_];         // gemm1 out [t,o,b]       33 MB
__device__ float g_s2[D_*D_*B_];         // spikes 2 [t,o,b]        33 MB
__device__ float g_y2[D_*C_*B_];         // gemm2 out [t,c,b]      128 MB
__device__ float g_mu1[D_], g_rs1[D_];
__device__ float g_mu2[C_], g_rs2[C_];

// ---------------- packed f32x2 FMA helpers (sm_103a FFMA2) ----------------
__device__ __forceinline__ unsigned long long pk2(float x, float y) {
    unsigned long long r;
    asm("mov.b64 %0, {%1, %2};" : "=l"(r) : "f"(x), "f"(y));
    return r;
}
__device__ __forceinline__ void fma2(unsigned long long &d, unsigned long long a,
                                     unsigned long long b) {
    asm("fma.rn.f32x2 %0, %1, %2, %0;" : "+l"(d) : "l"(a), "l"(b));
}
__device__ __forceinline__ void up2(unsigned long long v, float &a, float &b) {
    asm("mov.b64 {%0, %1}, %2;" : "=f"(a), "=f"(b) : "l"(v));
}

// ---------------- 1) LayerNorm over last dim (D=256), 1 warp/row ----------------
__global__ void ln_kernel(const float* __restrict__ x, const float* __restrict__ gam,
                          const float* __restrict__ bet) {
    int gw = (blockIdx.x * blockDim.x + threadIdx.x) >> 5;
    int lane = threadIdx.x & 31;
    if (gw >= ROWS) return;
    const float4* xr = (const float4*)(x + (size_t)gw * D_);
    float4 v0 = xr[lane];
    float4 v1 = xr[lane + 32];
    float s = v0.x + v0.y + v0.z + v0.w + v1.x + v1.y + v1.z + v1.w;
    float q = v0.x*v0.x + v0.y*v0.y + v0.z*v0.z + v0.w*v0.w
            + v1.x*v1.x + v1.y*v1.y + v1.z*v1.z + v1.w*v1.w;
    #pragma unroll
    for (int o = 16; o; o >>= 1) {
        s += __shfl_xor_sync(0xffffffffu, s, o);
        q += __shfl_xor_sync(0xffffffffu, q, o);
    }
    float mu = s * (1.0f / D_);
    float var = q * (1.0f / D_) - mu * mu;
    float rs = rsqrtf(var + 1e-5f);
    const float4* gg = (const float4*)gam;
    const float4* bb = (const float4*)bet;
    float4 g0 = gg[lane], g1 = gg[lane + 32];
    float4 b0 = bb[lane], b1 = bb[lane + 32];
    float4 o0, o1;
    o0.x = (v0.x - mu) * rs * g0.x + b0.x;
    o0.y = (v0.y - mu) * rs * g0.y + b0.y;
    o0.z = (v0.z - mu) * rs * g0.z + b0.z;
    o0.w = (v0.w - mu) * rs * g0.w + b0.w;
    o1.x = (v1.x - mu) * rs * g1.x + b1.x;
    o1.y = (v1.y - mu) * rs * g1.y + b1.y;
    o1.z = (v1.z - mu) * rs * g1.z + b1.z;
    o1.w = (v1.w - mu) * rs * g1.w + b1.w;
    float4* xo = (float4*)(g_xn + (size_t)gw * D_);
    xo[lane] = o0;
    xo[lane + 32] = o1;
}

// ---------------- 2/3) Mix-branch GEMM: C[m,n] = epi(sum_k A[m,k]*W[n,k]) ----------------
// BM=BN=128, BK=16, 256 threads, 8x8 microtile via FFMA2.
// EPI=0: A=g_xn, out=g_h, epi = relu(acc + bias[n])
// EPI=1: A=g_h,  out=Cout, epi = X[m,n] + acc + bias[n]
template <int EPI>
__global__ void __launch_bounds__(256) gemm_mix(const float* __restrict__ W,
                                                const float* __restrict__ bias,
                                                const float* __restrict__ X,
                                                float* __restrict__ Cout) {
    __shared__ float As[16][132];
    __shared__ float Bs[16][132];
    const float* A = (EPI == 0) ? g_xn : g_h;
    float* Cw = (EPI == 0) ? g_h : Cout;
    int m0 = blockIdx.x * 128;
    int n0 = blockIdx.y * 128;
    int tid = threadIdx.x;
    int tx = tid & 15, ty = tid >> 4;
    unsigned long long acc[8][4] = {};
    int lr = tid >> 2;
    int lk = (tid & 3) << 2;
    for (int k0 = 0; k0 < 256; k0 += 16) {
        #pragma unroll
        for (int p = 0; p < 2; p++) {
            float4 av = *(const float4*)(A + (size_t)(m0 + lr + p * 64) * 256 + k0 + lk);
            As[lk + 0][lr + p * 64] = av.x;
            As[lk + 1][lr + p * 64] = av.y;
            As[lk + 2][lr + p * 64] = av.z;
            As[lk + 3][lr + p * 64] = av.w;
            float4 wv = *(const float4*)(W + (size_t)(n0 + lr + p * 64) * 256 + k0 + lk);
            Bs[lk + 0][lr + p * 64] = wv.x;
            Bs[lk + 1][lr + p * 64] = wv.y;
            Bs[lk + 2][lr + p * 64] = wv.z;
            Bs[lk + 3][lr + p * 64] = wv.w;
        }
        __syncthreads();
        #pragma unroll
        for (int k = 0; k < 16; k++) {
            float a[8];
            *(float4*)(a)     = *(const float4*)&As[k][ty * 8];
            *(float4*)(a + 4) = *(const float4*)&As[k][ty * 8 + 4];
            unsigned long long bp[4];
            #pragma unroll
            for (int j = 0; j < 4; j++)
                bp[j] = *(const unsigned long long*)&Bs[k][tx * 8 + 2 * j];
            #pragma unroll
            for (int i = 0; i < 8; i++) {
                unsigned long long ad = pk2(a[i], a[i]);
                #pragma unroll
                for (int j = 0; j < 4; j++) fma2(acc[i][j], ad, bp[j]);
            }
        }
        __syncthreads();
    }
    #pragma unroll
    for (int i = 0; i < 8; i++) {
        int m = m0 + ty * 8 + i;
        int n = n0 + tx * 8;
        float o[8];
        #pragma unroll
        for (int j = 0; j < 4; j++) up2(acc[i][j], o[2 * j], o[2 * j + 1]);
        if (EPI == 0) {
            #pragma unroll
            for (int e = 0; e < 8; e++) o[e] = fmaxf(o[e] + bias[n + e], 0.0f);
        } else {
            const float* xp = X + (size_t)m * 256 + n;
            #pragma unroll
            for (int e = 0; e < 8; e++) o[e] = xp[e] + o[e] + bias[n + e];
        }
        float* cp = Cw + (size_t)m * 256 + n;
        *(float4*)(cp)     = make_float4(o[0], o[1], o[2], o[3]);
        *(float4*)(cp + 4) = make_float4(o[4], o[5], o[6], o[7]);
    }
}

// ---------------- 4) LIF over x (transposed view), writes s1[t,c,b] ----------------
__global__ void lif1_kernel(const float* __restrict__ x) {
    int tid = blockIdx.x * blockDim.x + threadIdx.x;
    int c = tid >> 7, b = tid & 127;
    const float4* xr = (const float4*)(x + ((size_t)b * C_ + c) * D_);
    float* sp = g_s1 + (size_t)c * B_ + b;
    float v = 0.0f;
    for (int q = 0; q < 64; q++) {
        float4 xv = xr[q];
        float xa[4] = {xv.x, xv.y, xv.z, xv.w};
        #pragma unroll
        for (int j = 0; j < 4; j++) {
            v = v + (xa[j] - v) * 0.5f;
            float s = (v >= 1.0f) ? 1.0f : 0.0f;
            sp[(size_t)(q * 4 + j) * CB] = s;
            if (v >= 1.0f) v = 0.0f;
        }
    }
}

// ---------------- 5/8) Spike GEMM: Y[t,m,n] = sum_k A[m,k]*S[t,k,n] + bias[m] ----------------
// PH=0: A=cw1 (M=256,K=1024), S=g_s1, Y=g_y1.  PH=1: A=cw2 (M=1024,K=256), S=g_s2, Y=g_y2.
template <int PH>
__global__ void __launch_bounds__(256) gemm_spike(const float* __restrict__ A,
                                                  const float* __restrict__ bias) {
    constexpr int M = (PH == 0) ? 256 : 1024;
    constexpr int K = (PH == 0) ? 1024 : 256;
    const float* S = (PH == 0) ? g_s1 : g_s2;
    float* Y = (PH == 0) ? g_y1 : g_y2;
    __shared__ float As[16][132];
    __shared__ float Bs[16][128];
    int t = blockIdx.y;
    int m0 = blockIdx.x * 128;
    const float* Sb = S + (size_t)t * K * B_;
    int tid = threadIdx.x;
    int tx = tid & 15, ty = tid >> 4;
    unsigned long long acc[8][4] = {};
    int lr = tid >> 2;
    int lk = (tid & 3) << 2;
    int bk = tid >> 4;          // 0..15
    int bn = (tid & 15) << 3;   // 0..120
    for (int k0 = 0; k0 < K; k0 += 16) {
        #pragma unroll
        for (int p = 0; p < 2; p++) {
            float4 av = *(const float4*)(A + (size_t)(m0 + lr + p * 64) * K + k0 + lk);
            As[lk + 0][lr + p * 64] = av.x;
            As[lk + 1][lr + p * 64] = av.y;
            As[lk + 2][lr + p * 64] = av.z;
            As[lk + 3][lr + p * 64] = av.w;
        }
        const float* srow = Sb + (size_t)(k0 + bk) * B_ + bn;
        float4 s0 = *(const float4*)(srow);
        float4 s1v = *(const float4*)(srow + 4);
        *(float4*)&Bs[bk][bn] = s0;
        *(float4*)&Bs[bk][bn + 4] = s1v;
        __syncthreads();
        #pragma unroll
        for (int k = 0; k < 16; k++) {
            float a[8];
            *(float4*)(a)     = *(const float4*)&As[k][ty * 8];
            *(float4*)(a + 4) = *(const float4*)&As[k][ty * 8 + 4];
            unsigned long long bp[4];
            #pragma unroll
            for (int j = 0; j < 4; j++)
                bp[j] = *(const unsigned long long*)&Bs[k][tx * 8 + 2 * j];
            #pragma unroll
            for (int i = 0; i < 8; i++) {
                unsigned long long ad = pk2(a[i], a[i]);
                #pragma unroll
                for (int j = 0; j < 4; j++) fma2(acc[i][j], ad, bp[j]);
            }
        }
        __syncthreads();
    }
    #pragma unroll
    for (int i = 0; i < 8; i++) {
        int m = m0 + ty * 8 + i;
        float bi = bias[m];
        float o[8];
        #pragma unroll
        for (int j = 0; j < 4; j++) up2(acc[i][j], o[2 * j], o[2 * j + 1]);
        #pragma unroll
        for (int e = 0; e < 8; e++) o[e] += bi;
        float* yp = Y + (size_t)t * M * B_ + (size_t)m * B_ + tx * 8;
        *(float4*)(yp)     = make_float4(o[0], o[1], o[2], o[3]);
        *(float4*)(yp + 4) = make_float4(o[4], o[5], o[6], o[7]);
    }
}

// ---------------- 6/9) BatchNorm stats over (t,b) per channel ----------------
template <int PH>
__global__ void bn_stats() {
    constexpr int M = (PH == 0) ? 256 : 1024;
    const float* Y = (PH == 0) ? g_y1 : g_y2;
    float* mu_o = (PH == 0) ? g_mu1 : g_mu2;
    float* rs_o = (PH == 0) ? g_rs1 : g_rs2;
    int m = blockIdx.x;
    const float* yp = Y + (size_t)m * B_;
    float s = 0.0f, q = 0.0f;
    for (int i = threadIdx.x; i < D_ * B_; i += 256) {
        int t = i >> 7, b = i & 127;
        float y = yp[(size_t)t * M * B_ + b];
        s += y;
        q += y * y;
    }
    #pragma unroll
    for (int o = 16; o; o >>= 1) {
        s += __shfl_xor_sync(0xffffffffu, s, o);
        q += __shfl_xor_sync(0xffffffffu, q, o);
    }
    __shared__ float ss[8], qq[8];
    int wid = threadIdx.x >> 5;
    if ((threadIdx.x & 31) == 0) { ss[wid] = s; qq[wid] = q; }
    __syncthreads();
    if (threadIdx.x == 0) {
        float S = 0.0f, Q = 0.0f;
        #pragma unroll
        for (int w = 0; w < 8; w++) { S += ss[w]; Q += qq[w]; }
        float mean = S * (1.0f / (D_ * B_));
        float var = Q * (1.0f / (D_ * B_)) - mean * mean;
        mu_o[m] = mean;
        rs_o[m] = rsqrtf(var + 1e-5f);
    }
}

// ---------------- 7) BN-apply + LIF over y1, writes s2[t,o,b] ----------------
__global__ void lif2_kernel(const float* __restrict__ gam, const float* __restrict__ bet) {
    int tid = blockIdx.x * blockDim.x + threadIdx.x;   // 32768
    int m = tid >> 7, b = tid & 127;
    float mu = g_mu1[m], rs = g_rs1[m], ga = gam[m], be = bet[m];
    const float* yp = g_y1 + (size_t)m * B_ + b;
    float* sp = g_s2 + (size_t)m * B_ + b;
    float v = 0.0f;
    for (int t = 0; t < D_; t++) {
        float y = yp[(size_t)t * OB];
        float yn = ((y - mu) * rs) * ga + be;
        v = v + (yn - v) * 0.5f;
        float s = (v >= 1.0f) ? 1.0f : 0.0f;
        sp[(size_t)t * OB] = s;
        if (v >= 1.0f) v = 0.0f;
    }
}

// ---------------- 10) BN2-apply + transpose + accumulate into out ----------------
__global__ void final_kernel(float* __restrict__ out, const float* __restrict__ gam,
                             const float* __restrict__ bet) {
    __shared__ float tile[32][33];
    int c = blockIdx.x;
    int t0 = blockIdx.y << 5;
    int b0 = blockIdx.z << 5;
    float mu = g_mu2[c], rs = g_rs2[c], ga = gam[c], be = bet[c];
    #pragma unroll
    for (int r = 0; r < 4; r++) {
        int t = t0 + threadIdx.y + r * 8;
        float y = g_y2[(size_t)t * CB + (size_t)c * B_ + b0 + threadIdx.x];
        tile[threadIdx.y + r * 8][threadIdx.x] = ((y - mu) * rs) * ga + be;
    }
    __syncthreads();
    #pragma unroll
    for (int r = 0; r < 4; r++) {
        int b = b0 + threadIdx.y + r * 8;
        size_t o = (size_t)b * (C_ * D_) + (size_t)c * D_ + t0 + threadIdx.x;
        out[o] += tile[threadIdx.x][threadIdx.y + r * 8];
    }
}

// ---------------- launch ----------------
extern "C" void kernel_launch(void* const* d_in, const int* in_sizes, int n_in,
                              void* d_out, int out_size) {
    const float* x    = (const float*)d_in[0];
    const float* ln_g = (const float*)d_in[1];
    const float* ln_b = (const float*)d_in[2];
    const float* w1   = (const float*)d_in[3];
    const float* b1   = (const float*)d_in[4];
    const float* w2   = (const float*)d_in[5];
    const float* b2   = (const float*)d_in[6];
    const float* cw1  = (const float*)d_in[7];
    const float* cb1  = (const float*)d_in[8];
    const float* bn1g = (const float*)d_in[9];
    const float* bn1b = (const float*)d_in[10];
    const float* cw2  = (const float*)d_in[11];
    const float* cb2  = (const float*)d_in[12];
    const float* bn2g = (const float*)d_in[13];
    const float* bn2b = (const float*)d_in[14];
    float* out = (float*)d_out;

    (void)in_sizes; (void)n_in; (void)out_size;

    // Mix branch (writes x1 into out)
    ln_kernel<<<ROWS / 8, 256>>>(x, ln_g, ln_b);
    gemm_mix<0><<<dim3(ROWS / 128, 2), 256>>>(w1, b1, nullptr, nullptr);
    gemm_mix<1><<<dim3(ROWS / 128, 2), 256>>>(w2, b2, x, out);

    // Spiking branch
    lif1_kernel<<<CB / 256, 256>>>(x);
    gemm_spike<0><<<dim3(2, D_), 256>>>(cw1, cb1);
    bn_stats<0><<<256, 256>>>();
    lif2_kernel<<<OB / 256, 256>>>(bn1g, bn1b);
    gemm_spike<1><<<dim3(8, D_), 256>>>(cw2, cb2);
    bn_stats<1><<<1024, 256>>>();
    final_kernel<<<dim3(C_, D_ / 32, B_ / 32), dim3(32, 8)>>>(out, bn2g, bn2b);
}

// round 6
// speedup vs baseline: 1.1638x; 1.1638x over previous
#include <cuda_runtime.h>
#include <cuda_bf16.h>
#include <cstdint>

#define B_ 128
#define C_ 1024
#define D_ 256
#define ROWS (B_*C_)
#define CB (C_*B_)
#define OB (D_*B_)

// ---------------- scratch ----------------
__device__ float g_xn[ROWS*D_];
__device__ float g_h [ROWS*D_];
__device__ float g_s1[D_*C_*B_];         // [t,c,b]
__device__ float g_y1[D_*D_*B_];
__device__ float g_s2[D_*D_*B_];
__device__ float g_y2[D_*C_*B_];
__device__ float g_mu1[D_], g_rs1[D_];
__device__ float g_mu2[C_], g_rs2[C_];

// ---------------- packed f32x2 FMA helpers ----------------
__device__ __forceinline__ unsigned long long pk2(float x, float y) {
    unsigned long long r;
    asm("mov.b64 %0, {%1, %2};" : "=l"(r) : "f"(x), "f"(y));
    return r;
}
__device__ __forceinline__ void fma2(unsigned long long &d, unsigned long long a,
                                     unsigned long long b) {
    asm("fma.rn.f32x2 %0, %1, %2, %0;" : "+l"(d) : "l"(a), "l"(b));
}
__device__ __forceinline__ void up2(unsigned long long v, float &a, float &b) {
    asm("mov.b64 {%0, %1}, %2;" : "=f"(a), "=f"(b) : "l"(v));
}

// ---------------- tensor-core helpers ----------------
__device__ __forceinline__ uint32_t smem_u32(const void* p) {
    uint32_t a;
    asm("{ .reg .u64 t; cvta.to.shared.u64 t, %1; cvt.u32.u64 %0, t; }" : "=r"(a) : "l"(p));
    return a;
}
__device__ __forceinline__ void ldm4(uint32_t* r, uint32_t a) {
    asm volatile("ldmatrix.sync.aligned.m8n8.x4.shared.b16 {%0,%1,%2,%3}, [%4];"
        : "=r"(r[0]), "=r"(r[1]), "=r"(r[2]), "=r"(r[3]) : "r"(a));
}
__device__ __forceinline__ void mma16816(float* c, const uint32_t* a, const uint32_t* b) {
    asm volatile("mma.sync.aligned.m16n8k16.row.col.f32.bf16.bf16.f32 "
        "{%0,%1,%2,%3},{%4,%5,%6,%7},{%8,%9},{%0,%1,%2,%3};"
        : "+f"(c[0]), "+f"(c[1]), "+f"(c[2]), "+f"(c[3])
        : "r"(a[0]), "r"(a[1]), "r"(a[2]), "r"(a[3]), "r"(b[0]), "r"(b[1]));
}
__device__ __forceinline__ int swz(int o) { return o ^ ((o >> 3) & 0x70); }
__device__ __forceinline__ void pack8(float* v, uint4& out, bool sub) {
    unsigned short h[8];
    #pragma unroll
    for (int j = 0; j < 8; j++) {
        __nv_bfloat16 b = __float2bfloat16(v[j]);
        h[j] = __bfloat16_as_ushort(b);
        if (sub) v[j] -= __bfloat162float(b);
    }
    out.x = h[0] | ((uint32_t)h[1] << 16);
    out.y = h[2] | ((uint32_t)h[3] << 16);
    out.z = h[4] | ((uint32_t)h[5] << 16);
    out.w = h[6] | ((uint32_t)h[7] << 16);
}

// ---------------- mix-branch tensor GEMM (2-split bf16, 3 passes) ----------------
// ID 0: g_xn @ w1^T + b1, relu -> g_h
// ID 1: g_h  @ w2^T + b2 + x -> out
template<int ID>
__global__ void __launch_bounds__(256)
gemm_mma(const float* __restrict__ Bfp, const float* __restrict__ bias,
         const float* __restrict__ X, float* __restrict__ outp) {
    constexpr int K = 256, NC = 8, PL = 8192, BUF = 4 * PL;
    extern __shared__ uint8_t smp[];
    const uint32_t sbase = smem_u32(smp);

    const int tid = threadIdx.x, lane = tid & 31, wid = tid >> 5;
    const int wm = wid >> 1, wn = wid & 1;
    const int lr = lane & 15, lc = (lane >> 4) << 4;
    const int m0 = blockIdx.x * 128;
    const int n0 = blockIdx.y * 128;

    const float* A = ((ID == 0) ? g_xn : g_h) + (size_t)m0 * K;
    const float* Bsrc = Bfp + (size_t)n0 * K;

    const int sr = tid >> 1, sc = (tid & 1) * 16;
    float sa[16], sbf[16];
    float acc[2][8][4] = {};

    auto LDG = [&](int kc) {
        const float* ap = A + (size_t)sr * K + kc + sc;
        #pragma unroll
        for (int q = 0; q < 4; q++) *(float4*)(sa + 4 * q) = *(const float4*)(ap + 4 * q);
        const float* bp = Bsrc + (size_t)sr * K + kc + sc;
        #pragma unroll
        for (int q = 0; q < 4; q++) *(float4*)(sbf + 4 * q) = *(const float4*)(bp + 4 * q);
    };
    auto STS = [&](int buf) {
        uint8_t* st = smp + buf * BUF;
        const int raw = sr * 64 + sc * 2;
        const int o0 = swz(raw), o1 = swz(raw + 16);
        #pragma unroll
        for (int s = 0; s < 2; s++) {
            uint4 u0, u1;
            pack8(sa,     u0, s == 0);
            pack8(sa + 8, u1, s == 0);
            *(uint4*)(st + s * PL + o0) = u0;
            *(uint4*)(st + s * PL + o1) = u1;
        }
        #pragma unroll
        for (int s = 0; s < 2; s++) {
            uint4 u0, u1;
            pack8(sbf,     u0, s == 0);
            pack8(sbf + 8, u1, s == 0);
            *(uint4*)(st + (2 + s) * PL + o0) = u0;
            *(uint4*)(st + (2 + s) * PL + o1) = u1;
        }
    };
    auto MMA = [&](int buf) {
        const uint32_t bs = sbase + buf * BUF;
        #pragma unroll
        for (int p = 0; p < 3; p++) {
            const int ia = (p == 2) ? 1 : 0;
            const int ib = (p == 1) ? 1 : 0;
            const uint32_t Ab = bs + ia * PL;
            const uint32_t Bb = bs + (2 + ib) * PL;
            #pragma unroll
            for (int ks = 0; ks < 2; ks++) {
                uint32_t a[2][4], bq[8][2];
                #pragma unroll
                for (int mi = 0; mi < 2; mi++) {
                    int raw = (wm * 32 + mi * 16 + lr) * 64 + ks * 32 + lc;
                    ldm4(a[mi], Ab + swz(raw));
                }
                #pragma unroll
                for (int nj = 0; nj < 4; nj++) {
                    int raw = (wn * 64 + nj * 16 + lr) * 64 + ks * 32 + lc;
                    uint32_t tq[4];
                    ldm4(tq, Bb + swz(raw));
                    bq[2*nj][0] = tq[0];   bq[2*nj][1] = tq[2];
                    bq[2*nj+1][0] = tq[1]; bq[2*nj+1][1] = tq[3];
                }
                #pragma unroll
                for (int mi = 0; mi < 2; mi++)
                    #pragma unroll
                    for (int nj = 0; nj < 8; nj++)
                        mma16816(acc[mi][nj], a[mi], bq[nj]);
            }
        }
    };

    LDG(0); STS(0); __syncthreads();
    for (int i = 0; i < NC; i++) {
        if (i + 1 < NC) LDG((i + 1) * 32);
        MMA(i & 1);
        if (i + 1 < NC) STS((i + 1) & 1);
        __syncthreads();
    }

    const int er = lane >> 2, ec = (lane & 3) * 2;
    #pragma unroll
    for (int mi = 0; mi < 2; mi++) {
        #pragma unroll
        for (int nj = 0; nj < 8; nj++) {
            float* c = acc[mi][nj];
            int m = m0 + wm * 32 + mi * 16 + er;
            int n = n0 + wn * 64 + nj * 8 + ec;
            float b0 = __ldg(bias + n), b1 = __ldg(bias + n + 1);
            if (ID == 0) {
                *(float2*)(g_h + (size_t)m * 256 + n) =
                    make_float2(fmaxf(c[0] + b0, 0.f), fmaxf(c[1] + b1, 0.f));
                *(float2*)(g_h + (size_t)(m + 8) * 256 + n) =
                    make_float2(fmaxf(c[2] + b0, 0.f), fmaxf(c[3] + b1, 0.f));
            } else {
                const float* x0 = X + (size_t)m * 256 + n;
                const float* x1 = X + (size_t)(m + 8) * 256 + n;
                *(float2*)(outp + (size_t)m * 256 + n) =
                    make_float2(c[0] + x0[0] + b0, c[1] + x0[1] + b1);
                *(float2*)(outp + (size_t)(m + 8) * 256 + n) =
                    make_float2(c[2] + x1[0] + b0, c[3] + x1[1] + b1);
            }
        }
    }
}

// ---------------- LayerNorm (R0 verbatim) ----------------
__global__ void ln_kernel(const float* __restrict__ x, const float* __restrict__ gam,
                          const float* __restrict__ bet) {
    int gw = (blockIdx.x * blockDim.x + threadIdx.x) >> 5;
    int lane = threadIdx.x & 31;
    if (gw >= ROWS) return;
    const float4* xr = (const float4*)(x + (size_t)gw * D_);
    float4 v0 = xr[lane], v1 = xr[lane + 32];
    float s = v0.x+v0.y+v0.z+v0.w + v1.x+v1.y+v1.z+v1.w;
    float q = v0.x*v0.x+v0.y*v0.y+v0.z*v0.z+v0.w*v0.w + v1.x*v1.x+v1.y*v1.y+v1.z*v1.z+v1.w*v1.w;
    #pragma unroll
    for (int o = 16; o; o >>= 1) {
        s += __shfl_xor_sync(0xffffffffu, s, o);
        q += __shfl_xor_sync(0xffffffffu, q, o);
    }
    float mu = s * (1.0f / D_);
    float var = q * (1.0f / D_) - mu * mu;
    float rs = rsqrtf(var + 1e-5f);
    const float4* gg = (const float4*)gam;
    const float4* bb = (const float4*)bet;
    float4 g0 = gg[lane], g1 = gg[lane + 32], b0 = bb[lane], b1 = bb[lane + 32];
    float4 o0, o1;
    o0.x=(v0.x-mu)*rs*g0.x+b0.x; o0.y=(v0.y-mu)*rs*g0.y+b0.y;
    o0.z=(v0.z-mu)*rs*g0.z+b0.z; o0.w=(v0.w-mu)*rs*g0.w+b0.w;
    o1.x=(v1.x-mu)*rs*g1.x+b1.x; o1.y=(v1.y-mu)*rs*g1.y+b1.y;
    o1.z=(v1.z-mu)*rs*g1.z+b1.z; o1.w=(v1.w-mu)*rs*g1.w+b1.w;
    float4* xo = (float4*)(g_xn + (size_t)gw * D_);
    xo[lane] = o0; xo[lane + 32] = o1;
}

// ---------------- LIF 1 (R0 verbatim) ----------------
__global__ void lif1_kernel(const float* __restrict__ x) {
    int tid = blockIdx.x * blockDim.x + threadIdx.x;
    int c = tid >> 7, b = tid & 127;
    const float4* xr = (const float4*)(x + ((size_t)b * C_ + c) * D_);
    float* sp = g_s1 + (size_t)c * B_ + b;
    float v = 0.0f;
    for (int q = 0; q < 64; q++) {
        float4 xv = xr[q];
        float xa[4] = {xv.x, xv.y, xv.z, xv.w};
        #pragma unroll
        for (int j = 0; j < 4; j++) {
            v = v + (xa[j] - v) * 0.5f;
            float s = (v >= 1.0f) ? 1.0f : 0.0f;
            sp[(size_t)(q * 4 + j) * CB] = s;
            if (v >= 1.0f) v = 0.0f;
        }
    }
}

// ---------------- Spike GEMM (R0 verbatim, FFMA) ----------------
template <int PH>
__global__ void __launch_bounds__(256) gemm_spike(const float* __restrict__ A,
                                                  const float* __restrict__ bias) {
    constexpr int M = (PH == 0) ? 256 : 1024;
    constexpr int K = (PH == 0) ? 1024 : 256;
    const float* S = (PH == 0) ? g_s1 : g_s2;
    float* Y = (PH == 0) ? g_y1 : g_y2;
    __shared__ float As[16][132];
    __shared__ float Bs[16][128];
    int t = blockIdx.y;
    int m0 = blockIdx.x * 128;
    const float* Sb = S + (size_t)t * K * B_;
    int tid = threadIdx.x;
    int tx = tid & 15, ty = tid >> 4;
    unsigned long long acc[8][4] = {};
    int lr = tid >> 2;
    int lk = (tid & 3) << 2;
    int bk = tid >> 4;
    int bn = (tid & 15) << 3;
    for (int k0 = 0; k0 < K; k0 += 16) {
        #pragma unroll
        for (int p = 0; p < 2; p++) {
            float4 av = *(const float4*)(A + (size_t)(m0 + lr + p * 64) * K + k0 + lk);
            As[lk + 0][lr + p * 64] = av.x;
            As[lk + 1][lr + p * 64] = av.y;
            As[lk + 2][lr + p * 64] = av.z;
            As[lk + 3][lr + p * 64] = av.w;
        }
        const float* srow = Sb + (size_t)(k0 + bk) * B_ + bn;
        float4 s0 = *(const float4*)(srow);
        float4 s1v = *(const float4*)(srow + 4);
        *(float4*)&Bs[bk][bn] = s0;
        *(float4*)&Bs[bk][bn + 4] = s1v;
        __syncthreads();
        #pragma unroll
        for (int k = 0; k < 16; k++) {
            float a[8];
            *(float4*)(a)     = *(const float4*)&As[k][ty * 8];
            *(float4*)(a + 4) = *(const float4*)&As[k][ty * 8 + 4];
            unsigned long long bp[4];
            #pragma unroll
            for (int j = 0; j < 4; j++)
                bp[j] = *(const unsigned long long*)&Bs[k][tx * 8 + 2 * j];
            #pragma unroll
            for (int i = 0; i < 8; i++) {
                unsigned long long ad = pk2(a[i], a[i]);
                #pragma unroll
                for (int j = 0; j < 4; j++) fma2(acc[i][j], ad, bp[j]);
            }
        }
        __syncthreads();
    }
    #pragma unroll
    for (int i = 0; i < 8; i++) {
        int m = m0 + ty * 8 + i;
        float bi = bias[m];
        float o[8];
        #pragma unroll
        for (int j = 0; j < 4; j++) up2(acc[i][j], o[2 * j], o[2 * j + 1]);
        #pragma unroll
        for (int e = 0; e < 8; e++) o[e] += bi;
        float* yp = Y + (size_t)t * M * B_ + (size_t)m * B_ + tx * 8;
        *(float4*)(yp)     = make_float4(o[0], o[1], o[2], o[3]);
        *(float4*)(yp + 4) = make_float4(o[4], o[5], o[6], o[7]);
    }
}

// ---------------- BN stats (R0 verbatim) ----------------
template <int PH>
__global__ void bn_stats() {
    constexpr int M = (PH == 0) ? 256 : 1024;
    const float* Y = (PH == 0) ? g_y1 : g_y2;
    float* mu_o = (PH == 0) ? g_mu1 : g_mu2;
    float* rs_o = (PH == 0) ? g_rs1 : g_rs2;
    int m = blockIdx.x;
    const float* yp = Y + (size_t)m * B_;
    float s = 0.0f, q = 0.0f;
    for (int i = threadIdx.x; i < D_ * B_; i += 256) {
        float y = yp[(size_t)(i >> 7) * M * B_ + (i & 127)];
        s += y; q += y * y;
    }
    #pragma unroll
    for (int o = 16; o; o >>= 1) {
        s += __shfl_xor_sync(0xffffffffu, s, o);
        q += __shfl_xor_sync(0xffffffffu, q, o);
    }
    __shared__ float ss[8], qq[8];
    int wid = threadIdx.x >> 5;
    if ((threadIdx.x & 31) == 0) { ss[wid] = s; qq[wid] = q; }
    __syncthreads();
    if (threadIdx.x == 0) {
        float S = 0.0f, Q = 0.0f;
        #pragma unroll
        for (int w = 0; w < 8; w++) { S += ss[w]; Q += qq[w]; }
        float mean = S * (1.0f / (D_ * B_));
        float var = Q * (1.0f / (D_ * B_)) - mean * mean;
        mu_o[m] = mean;
        rs_o[m] = rsqrtf(var + 1e-5f);
    }
}

// ---------------- BN1 + LIF 2 (R0 verbatim) ----------------
__global__ void lif2_kernel(const float* __restrict__ gam, const float* __restrict__ bet) {
    int tid = blockIdx.x * blockDim.x + threadIdx.x;
    int m = tid >> 7, b = tid & 127;
    float mu = g_mu1[m], rs = g_rs1[m], ga = gam[m], be = bet[m];
    const float* yp = g_y1 + (size_t)m * B_ + b;
    float* sp = g_s2 + (size_t)m * B_ + b;
    float v = 0.0f;
    for (int t = 0; t < D_; t++) {
        float y = yp[(size_t)t * OB];
        float yn = ((y - mu) * rs) * ga + be;
        v = v + (yn - v) * 0.5f;
        float s = (v >= 1.0f) ? 1.0f : 0.0f;
        sp[(size_t)t * OB] = s;
        if (v >= 1.0f) v = 0.0f;
    }
}

// ---------------- BN2 + transpose + accumulate (R0 verbatim) ----------------
__global__ void final_kernel(float* __restrict__ out, const float* __restrict__ gam,
                             const float* __restrict__ bet) {
    __shared__ float tile[32][33];
    int c = blockIdx.x;
    int t0 = blockIdx.y << 5, b0 = blockIdx.z << 5;
    float mu = g_mu2[c], rs = g_rs2[c], ga = gam[c], be = bet[c];
    #pragma unroll
    for (int r = 0; r < 4; r++) {
        int t = t0 + threadIdx.y + r * 8;
        float y = g_y2[(size_t)t * CB + (size_t)c * B_ + b0 + threadIdx.x];
        tile[threadIdx.y + r * 8][threadIdx.x] = ((y - mu) * rs) * ga + be;
    }
    __syncthreads();
    #pragma unroll
    for (int r = 0; r < 4; r++) {
        int b = b0 + threadIdx.y + r * 8;
        size_t o = (size_t)b * (C_ * D_) + (size_t)c * D_ + t0 + threadIdx.x;
        out[o] += tile[threadIdx.x][threadIdx.y + r * 8];
    }
}

// ---------------- launch ----------------
extern "C" void kernel_launch(void* const* d_in, const int* in_sizes, int n_in,
                              void* d_out, int out_size) {
    const float* x    = (const float*)d_in[0];
    const float* ln_g = (const float*)d_in[1];
    const float* ln_b = (const float*)d_in[2];
    const float* w1   = (const float*)d_in[3];
    const float* b1   = (const float*)d_in[4];
    const float* w2   = (const float*)d_in[5];
    const float* b2   = (const float*)d_in[6];
    const float* cw1  = (const float*)d_in[7];
    const float* cb1  = (const float*)d_in[8];
    const float* bn1g = (const float*)d_in[9];
    const float* bn1b = (const float*)d_in[10];
    const float* cw2  = (const float*)d_in[11];
    const float* cb2  = (const float*)d_in[12];
    const float* bn2g = (const float*)d_in[13];
    const float* bn2b = (const float*)d_in[14];
    float* out = (float*)d_out;
    (void)in_sizes; (void)n_in; (void)out_size;

    const int sm4 = 2 * 4 * 8192;   // 65536
    cudaFuncSetAttribute(gemm_mma<0>, cudaFuncAttributeMaxDynamicSharedMemorySize, sm4);
    cudaFuncSetAttribute(gemm_mma<1>, cudaFuncAttributeMaxDynamicSharedMemorySize, sm4);

    // Mix branch: tensor cores
    ln_kernel<<<ROWS / 8, 256>>>(x, ln_g, ln_b);
    gemm_mma<0><<<dim3(1024, 2), 256, sm4>>>(w1, b1, nullptr, nullptr);
    gemm_mma<1><<<dim3(1024, 2), 256, sm4>>>(w2, b2, x, out);

    // Spiking branch: R0-proven FFMA path
    lif1_kernel<<<CB / 256, 256>>>(x);
    gemm_spike<0><<<dim3(2, D_), 256>>>(cw1, cb1);
    bn_stats<0><<<256, 256>>>();
    lif2_kernel<<<OB / 256, 256>>>(bn1g, bn1b);
    gemm_spike<1><<<dim3(8, D_), 256>>>(cw2, cb2);
    bn_stats<1><<<1024, 256>>>();
    final_kernel<<<dim3(C_, D_ / 32, B_ / 32), dim3(32, 8)>>>(out, bn2g, bn2b);
}

// round 7
// speedup vs baseline: 1.4550x; 1.2502x over previous
#include <cuda_runtime.h>
#include <cuda_bf16.h>
#include <cstdint>

#define B_ 128
#define C_ 1024
#define D_ 256
#define ROWS (B_*C_)
#define CB (C_*B_)

// ---------------- scratch ----------------
__device__ float g_xn[ROWS*D_];
__device__ float g_h [ROWS*D_];
__device__ float g_s1t[D_*B_*C_];   // spikes1 [t][b][c]
__device__ float g_y1 [D_*B_*D_];   // gemm1 out [t][b][o]
__device__ float g_s2t[D_*B_*D_];   // spikes2 [t][b][o]
__device__ float g_y2 [D_*B_*C_];   // gemm2 out [t][b][c]
__device__ float g_pS[D_*C_], g_pQ[D_*C_];
__device__ float g_mu1[D_], g_rs1[D_], g_mu2[C_], g_rs2[C_];

// ---------------- tensor-core helpers (proven R6) ----------------
__device__ __forceinline__ uint32_t smem_u32(const void* p) {
    uint32_t a;
    asm("{ .reg .u64 t; cvta.to.shared.u64 t, %1; cvt.u32.u64 %0, t; }" : "=r"(a) : "l"(p));
    return a;
}
__device__ __forceinline__ void ldm4(uint32_t* r, uint32_t a) {
    asm volatile("ldmatrix.sync.aligned.m8n8.x4.shared.b16 {%0,%1,%2,%3}, [%4];"
        : "=r"(r[0]), "=r"(r[1]), "=r"(r[2]), "=r"(r[3]) : "r"(a));
}
__device__ __forceinline__ void mma16816(float* c, const uint32_t* a, const uint32_t* b) {
    asm volatile("mma.sync.aligned.m16n8k16.row.col.f32.bf16.bf16.f32 "
        "{%0,%1,%2,%3},{%4,%5,%6,%7},{%8,%9},{%0,%1,%2,%3};"
        : "+f"(c[0]), "+f"(c[1]), "+f"(c[2]), "+f"(c[3])
        : "r"(a[0]), "r"(a[1]), "r"(a[2]), "r"(a[3]), "r"(b[0]), "r"(b[1]));
}
__device__ __forceinline__ int swz(int o) { return o ^ ((o >> 3) & 0x70); }
__device__ __forceinline__ void pack8(float* v, uint4& out, bool sub) {
    unsigned short h[8];
    #pragma unroll
    for (int j = 0; j < 8; j++) {
        __nv_bfloat16 b = __float2bfloat16(v[j]);
        h[j] = __bfloat16_as_ushort(b);
        if (sub) v[j] -= __bfloat162float(b);
    }
    out.x = h[0] | ((uint32_t)h[1] << 16);
    out.y = h[2] | ((uint32_t)h[3] << 16);
    out.z = h[4] | ((uint32_t)h[5] << 16);
    out.w = h[6] | ((uint32_t)h[7] << 16);
}

// ---------------- universal split-bf16 mma.sync GEMM ----------------
// ID 0: g_xn  @ w1^T  + b1, relu -> g_h                (A 2-split, B 2-split, 3 passes)
// ID 1: g_h   @ w2^T  + b2 + x  -> out                 (A 2-split, B 2-split, 3 passes)
// ID 2: s1t[t] @ cw1^T + cb1    -> g_y1[t] (ld 256)    (A exact,   B 3-split, 3 passes)
// ID 3: s2t[t] @ cw2^T + cb2    -> g_y2[t] (ld 1024)   (A exact,   B 2-split, 2 passes)
template<int ID>
__global__ void __launch_bounds__(256)
gemm_mma(const float* __restrict__ Bfp, const float* __restrict__ bias,
         const float* __restrict__ X, float* __restrict__ outp) {
    constexpr int K   = (ID == 2) ? 1024 : 256;
    constexpr int NA  = (ID < 2) ? 2 : 1;
    constexpr int NBS = (ID == 2) ? 3 : 2;
    constexpr int NP  = (ID == 3) ? 2 : 3;
    constexpr int LDC = (ID == 3) ? 1024 : 256;
    constexpr int NC  = K / 32;
    constexpr int PL  = 8192;
    constexpr int BUF = (NA + NBS) * PL;
    extern __shared__ uint8_t smp[];
    const uint32_t sbase = smem_u32(smp);

    const int tid = threadIdx.x, lane = tid & 31, wid = tid >> 5;
    const int wm = wid >> 1, wn = wid & 1;
    const int lr = lane & 15, lc = (lane >> 4) << 4;
    const int m0 = blockIdx.x * 128;
    const int n0 = blockIdx.y * 128;
    const int z  = blockIdx.z;

    const float* A =
        (ID == 0) ? g_xn + (size_t)m0 * K :
        (ID == 1) ? g_h  + (size_t)m0 * K :
        (ID == 2) ? g_s1t + (size_t)z * (B_ * C_) :
                    g_s2t + (size_t)z * (B_ * D_);
    const float* Bsrc = Bfp + (size_t)n0 * K;
    float* outb =
        (ID == 0) ? g_h :
        (ID == 1) ? outp :
        (ID == 2) ? g_y1 + (size_t)z * (B_ * 256) :
                    g_y2 + (size_t)z * (B_ * 1024);

    const int sr = tid >> 1, sc = (tid & 1) * 16;
    float sa[16], sbf[16];
    float acc[2][8][4] = {};

    auto LDG = [&](int kc) {
        const float* ap = A + (size_t)sr * K + kc + sc;
        #pragma unroll
        for (int q = 0; q < 4; q++) *(float4*)(sa + 4 * q) = *(const float4*)(ap + 4 * q);
        const float* bp = Bsrc + (size_t)sr * K + kc + sc;
        #pragma unroll
        for (int q = 0; q < 4; q++) *(float4*)(sbf + 4 * q) = *(const float4*)(bp + 4 * q);
    };
    auto STS = [&](int buf) {
        uint8_t* st = smp + buf * BUF;
        const int raw = sr * 64 + sc * 2;
        const int o0 = swz(raw), o1 = swz(raw + 16);
        #pragma unroll
        for (int s = 0; s < NA; s++) {
            uint4 u0, u1;
            pack8(sa,     u0, s + 1 < NA);
            pack8(sa + 8, u1, s + 1 < NA);
            *(uint4*)(st + s * PL + o0) = u0;
            *(uint4*)(st + s * PL + o1) = u1;
        }
        #pragma unroll
        for (int s = 0; s < NBS; s++) {
            uint4 u0, u1;
            pack8(sbf,     u0, s + 1 < NBS);
            pack8(sbf + 8, u1, s + 1 < NBS);
            *(uint4*)(st + (NA + s) * PL + o0) = u0;
            *(uint4*)(st + (NA + s) * PL + o1) = u1;
        }
    };
    auto MMA = [&](int buf) {
        const uint32_t bs = sbase + buf * BUF;
        #pragma unroll
        for (int p = 0; p < NP; p++) {
            const int ia = (ID < 2) ? ((p == 2) ? 1 : 0) : 0;
            const int ib = (ID < 2) ? ((p == 1) ? 1 : 0) : p;
            const uint32_t Ab = bs + ia * PL;
            const uint32_t Bb = bs + (NA + ib) * PL;
            #pragma unroll
            for (int ks = 0; ks < 2; ks++) {
                uint32_t a[2][4], bq[8][2];
                #pragma unroll
                for (int mi = 0; mi < 2; mi++) {
                    int raw = (wm * 32 + mi * 16 + lr) * 64 + ks * 32 + lc;
                    ldm4(a[mi], Ab + swz(raw));
                }
                #pragma unroll
                for (int nj = 0; nj < 4; nj++) {
                    int raw = (wn * 64 + nj * 16 + lr) * 64 + ks * 32 + lc;
                    uint32_t tq[4];
                    ldm4(tq, Bb + swz(raw));
                    bq[2*nj][0] = tq[0];   bq[2*nj][1] = tq[2];
                    bq[2*nj+1][0] = tq[1]; bq[2*nj+1][1] = tq[3];
                }
                #pragma unroll
                for (int mi = 0; mi < 2; mi++)
                    #pragma unroll
                    for (int nj = 0; nj < 8; nj++)
                        mma16816(acc[mi][nj], a[mi], bq[nj]);
            }
        }
    };

    LDG(0); STS(0); __syncthreads();
    for (int i = 0; i < NC; i++) {
        if (i + 1 < NC) LDG((i + 1) * 32);
        MMA(i & 1);
        if (i + 1 < NC) STS((i + 1) & 1);
        __syncthreads();
    }

    const int er = lane >> 2, ec = (lane & 3) * 2;
    #pragma unroll
    for (int mi = 0; mi < 2; mi++) {
        #pragma unroll
        for (int nj = 0; nj < 8; nj++) {
            float* c = acc[mi][nj];
            int m = m0 + wm * 32 + mi * 16 + er;
            int n = n0 + wn * 64 + nj * 8 + ec;
            float b0 = __ldg(bias + n), b1 = __ldg(bias + n + 1);
            float* o0p = outb + (size_t)m * LDC + n;
            float* o1p = outb + (size_t)(m + 8) * LDC + n;
            if (ID == 0) {
                *(float2*)o0p = make_float2(fmaxf(c[0] + b0, 0.f), fmaxf(c[1] + b1, 0.f));
                *(float2*)o1p = make_float2(fmaxf(c[2] + b0, 0.f), fmaxf(c[3] + b1, 0.f));
            } else if (ID == 1) {
                const float* x0 = X + (size_t)m * 256 + n;
                const float* x1 = X + (size_t)(m + 8) * 256 + n;
                *(float2*)o0p = make_float2(c[0] + x0[0] + b0, c[1] + x0[1] + b1);
                *(float2*)o1p = make_float2(c[2] + x1[0] + b0, c[3] + x1[1] + b1);
            } else {
                *(float2*)o0p = make_float2(c[0] + b0, c[1] + b1);
                *(float2*)o1p = make_float2(c[2] + b0, c[3] + b1);
            }
        }
    }
}

// ---------------- LayerNorm (proven) ----------------
__global__ void ln_kernel(const float* __restrict__ x, const float* __restrict__ gam,
                          const float* __restrict__ bet) {
    int gw = (blockIdx.x * blockDim.x + threadIdx.x) >> 5;
    int lane = threadIdx.x & 31;
    if (gw >= ROWS) return;
    const float4* xr = (const float4*)(x + (size_t)gw * D_);
    float4 v0 = xr[lane], v1 = xr[lane + 32];
    float s = v0.x+v0.y+v0.z+v0.w + v1.x+v1.y+v1.z+v1.w;
    float q = v0.x*v0.x+v0.y*v0.y+v0.z*v0.z+v0.w*v0.w + v1.x*v1.x+v1.y*v1.y+v1.z*v1.z+v1.w*v1.w;
    #pragma unroll
    for (int o = 16; o; o >>= 1) {
        s += __shfl_xor_sync(0xffffffffu, s, o);
        q += __shfl_xor_sync(0xffffffffu, q, o);
    }
    float mu = s * (1.0f / D_);
    float rs = rsqrtf(q * (1.0f / D_) - mu * mu + 1e-5f);
    const float4* gg = (const float4*)gam;
    const float4* bb = (const float4*)bet;
    float4 g0 = gg[lane], g1 = gg[lane + 32], b0 = bb[lane], b1 = bb[lane + 32];
    float4 o0, o1;
    o0.x=(v0.x-mu)*rs*g0.x+b0.x; o0.y=(v0.y-mu)*rs*g0.y+b0.y;
    o0.z=(v0.z-mu)*rs*g0.z+b0.z; o0.w=(v0.w-mu)*rs*g0.w+b0.w;
    o1.x=(v1.x-mu)*rs*g1.x+b1.x; o1.y=(v1.y-mu)*rs*g1.y+b1.y;
    o1.z=(v1.z-mu)*rs*g1.z+b1.z; o1.w=(v1.w-mu)*rs*g1.w+b1.w;
    float4* xo = (float4*)(g_xn + (size_t)gw * D_);
    xo[lane] = o0; xo[lane + 32] = o1;
}

// ---------------- LIF 1: x[b][c][t] -> s1t[t][b][c] ----------------
__global__ void lif1_kernel(const float* __restrict__ x) {
    int tid = blockIdx.x * blockDim.x + threadIdx.x;   // 131072
    int b = tid >> 10, c = tid & 1023;
    const float4* xr = (const float4*)(x + ((size_t)b * C_ + c) * D_);
    float* sp = g_s1t + (size_t)b * C_ + c;
    float v = 0.0f;
    for (int q = 0; q < 64; q++) {
        float4 xv = xr[q];
        float xa[4] = {xv.x, xv.y, xv.z, xv.w};
        #pragma unroll
        for (int j = 0; j < 4; j++) {
            v = v + (xa[j] - v) * 0.5f;
            float s = (v >= 1.0f) ? 1.0f : 0.0f;
            sp[(size_t)(q * 4 + j) * CB] = s;
            if (v >= 1.0f) v = 0.0f;
        }
    }
}

// ---------------- BN stats: stage 1 (per-t slab partials) ----------------
template<int M>
__global__ void bn_slab() {
    const float* Y = (M == 256) ? g_y1 : g_y2;
    int t = blockIdx.x, tid = threadIdx.x;
    constexpr int R = M / 256;
    float s[R], q[R];
    #pragma unroll
    for (int r = 0; r < R; r++) { s[r] = 0.0f; q[r] = 0.0f; }
    const float* base = Y + (size_t)t * 128 * M;
    for (int b = 0; b < 128; b++) {
        const float* row = base + (size_t)b * M;
        #pragma unroll
        for (int r = 0; r < R; r++) {
            float v = row[tid + r * 256];
            s[r] += v; q[r] += v * v;
        }
    }
    #pragma unroll
    for (int r = 0; r < R; r++) {
        g_pS[(size_t)t * M + tid + r * 256] = s[r];
        g_pQ[(size_t)t * M + tid + r * 256] = q[r];
    }
}

// ---------------- BN stats: stage 2 (reduce over t) ----------------
template<int M>
__global__ void bn_reduce() {
    int c = blockIdx.x * 256 + threadIdx.x;
    float S = 0.0f, Q = 0.0f;
    for (int t = 0; t < 256; t++) {
        S += g_pS[(size_t)t * M + c];
        Q += g_pQ[(size_t)t * M + c];
    }
    float mean = S * (1.0f / 32768.0f);
    float var = Q * (1.0f / 32768.0f) - mean * mean;
    float rs = rsqrtf(var + 1e-5f);
    if (M == 256) { g_mu1[c] = mean; g_rs1[c] = rs; }
    else          { g_mu2[c] = mean; g_rs2[c] = rs; }
}

// ---------------- BN1 + LIF 2: y1[t][b][o] -> s2t[t][b][o] ----------------
__global__ void lif2_kernel(const float* __restrict__ gam, const float* __restrict__ bet) {
    int tid = blockIdx.x * blockDim.x + threadIdx.x;   // 32768
    int b = tid >> 8, o = tid & 255;
    float mu = g_mu1[o], rs = g_rs1[o], ga = gam[o], be = bet[o];
    const float* yp = g_y1 + (size_t)b * 256 + o;
    float* sp = g_s2t + (size_t)b * 256 + o;
    float v = 0.0f;
    for (int t = 0; t < D_; t++) {
        float yn = ((yp[(size_t)t * 32768] - mu) * rs) * ga + be;
        v = v + (yn - v) * 0.5f;
        float s = (v >= 1.0f) ? 1.0f : 0.0f;
        sp[(size_t)t * 32768] = s;
        if (v >= 1.0f) v = 0.0f;
    }
}

// ---------------- BN2 + transpose(t,c) + accumulate into out[b][c][t] ----------------
__global__ void final_kernel(float* __restrict__ out, const float* __restrict__ gam,
                             const float* __restrict__ bet) {
    __shared__ float tile[32][33];
    int b = blockIdx.x;
    int c0 = blockIdx.y << 5, t0 = blockIdx.z << 5;
    #pragma unroll
    for (int i = 0; i < 4; i++) {
        int t = t0 + threadIdx.y + i * 8;
        tile[threadIdx.y + i * 8][threadIdx.x] =
            g_y2[(size_t)t * (B_ * 1024) + (size_t)b * 1024 + c0 + threadIdx.x];
    }
    __syncthreads();
    #pragma unroll
    for (int i = 0; i < 4; i++) {
        int c = c0 + threadIdx.y + i * 8;
        float mu = g_mu2[c], rs = g_rs2[c], ga = __ldg(gam + c), be = __ldg(bet + c);
        size_t o = (size_t)b * (C_ * D_) + (size_t)c * D_ + t0 + threadIdx.x;
        out[o] += (tile[threadIdx.x][threadIdx.y + i * 8] - mu) * rs * ga + be;
    }
}

// ---------------- launch ----------------
extern "C" void kernel_launch(void* const* d_in, const int* in_sizes, int n_in,
                              void* d_out, int out_size) {
    const float* x    = (const float*)d_in[0];
    const float* ln_g = (const float*)d_in[1];
    const float* ln_b = (const float*)d_in[2];
    const float* w1   = (const float*)d_in[3];
    const float* b1   = (const float*)d_in[4];
    const float* w2   = (const float*)d_in[5];
    const float* b2   = (const float*)d_in[6];
    const float* cw1  = (const float*)d_in[7];
    const float* cb1  = (const float*)d_in[8];
    const float* bn1g = (const float*)d_in[9];
    const float* bn1b = (const float*)d_in[10];
    const float* cw2  = (const float*)d_in[11];
    const float* cb2  = (const float*)d_in[12];
    const float* bn2g = (const float*)d_in[13];
    const float* bn2b = (const float*)d_in[14];
    float* out = (float*)d_out;
    (void)in_sizes; (void)n_in; (void)out_size;

    const int sm4 = 2 * 4 * 8192;   // 65536 (IDs 0,1,2)
    const int sm3 = 2 * 3 * 8192;   // 49152 (ID 3)
    cudaFuncSetAttribute(gemm_mma<0>, cudaFuncAttributeMaxDynamicSharedMemorySize, sm4);
    cudaFuncSetAttribute(gemm_mma<1>, cudaFuncAttributeMaxDynamicSharedMemorySize, sm4);
    cudaFuncSetAttribute(gemm_mma<2>, cudaFuncAttributeMaxDynamicSharedMemorySize, sm4);
    cudaFuncSetAttribute(gemm_mma<3>, cudaFuncAttributeMaxDynamicSharedMemorySize, sm3);

    // Mix branch (tensor cores, proven)
    ln_kernel<<<ROWS / 8, 256>>>(x, ln_g, ln_b);
    gemm_mma<0><<<dim3(1024, 2), 256, sm4>>>(w1, b1, nullptr, nullptr);
    gemm_mma<1><<<dim3(1024, 2), 256, sm4>>>(w2, b2, x, out);

    // Spiking branch (tensor cores, spikes as exact-bf16 A operand)
    lif1_kernel<<<CB / 256, 256>>>(x);
    gemm_mma<2><<<dim3(1, 2, 256), 256, sm4>>>(cw1, cb1, nullptr, nullptr);
    bn_slab<256><<<256, 256>>>();
    bn_reduce<256><<<1, 256>>>();
    lif2_kernel<<<128, 256>>>(bn1g, bn1b);
    gemm_mma<3><<<dim3(1, 8, 256), 256, sm3>>>(cw2, cb2, nullptr, nullptr);
    bn_slab<1024><<<256, 256>>>();
    bn_reduce<1024><<<4, 256>>>();
    final_kernel<<<dim3(B_, C_ / 32, D_ / 32), dim3(32, 8)>>>(out, bn2g, bn2b);
}

// round 10
// speedup vs baseline: 1.8471x; 1.2695x over previous
#include <cuda_runtime.h>
#include <cuda_fp16.h>
#include <cuda_bf16.h>
#include <cstdint>

#define B_ 128
#define C_ 1024
#define D_ 256
#define ROWS (B_*C_)
#define CB (C_*B_)

// ---------------- scratch ----------------
__device__ __half g_xn[ROWS*D_];
__device__ __half g_h [ROWS*D_];
__device__ __nv_bfloat16 g_s1t[D_*B_*C_];   // spikes1 [t][b][c] (bf16, exact)
__device__ __nv_bfloat16 g_s2t[D_*B_*D_];   // spikes2 [t][b][o]
__device__ float g_y1 [D_*B_*D_];           // gemm1 out [t][b][o]
__device__ float g_y2 [D_*B_*C_];           // gemm2 out [t][b][c]
__device__ float g_pS[D_*C_], g_pQ[D_*C_];
__device__ float g_mu1[D_], g_rs1[D_], g_mu2[C_], g_rs2[C_];

// ---------------- tensor-core helpers ----------------
__device__ __forceinline__ uint32_t smem_u32(const void* p) {
    uint32_t a;
    asm("{ .reg .u64 t; cvta.to.shared.u64 t, %1; cvt.u32.u64 %0, t; }" : "=r"(a) : "l"(p));
    return a;
}
__device__ __forceinline__ void ldm4(uint32_t* r, uint32_t a) {
    asm volatile("ldmatrix.sync.aligned.m8n8.x4.shared.b16 {%0,%1,%2,%3}, [%4];"
        : "=r"(r[0]), "=r"(r[1]), "=r"(r[2]), "=r"(r[3]) : "r"(a));
}
template<bool BF>
__device__ __forceinline__ void mma16816(float* c, const uint32_t* a, const uint32_t* b) {
    if (BF)
        asm volatile("mma.sync.aligned.m16n8k16.row.col.f32.bf16.bf16.f32 "
            "{%0,%1,%2,%3},{%4,%5,%6,%7},{%8,%9},{%0,%1,%2,%3};"
            : "+f"(c[0]), "+f"(c[1]), "+f"(c[2]), "+f"(c[3])
            : "r"(a[0]), "r"(a[1]), "r"(a[2]), "r"(a[3]), "r"(b[0]), "r"(b[1]));
    else
        asm volatile("mma.sync.aligned.m16n8k16.row.col.f32.f16.f16.f32 "
            "{%0,%1,%2,%3},{%4,%5,%6,%7},{%8,%9},{%0,%1,%2,%3};"
            : "+f"(c[0]), "+f"(c[1]), "+f"(c[2]), "+f"(c[3])
            : "r"(a[0]), "r"(a[1]), "r"(a[2]), "r"(a[3]), "r"(b[0]), "r"(b[1]));
}
__device__ __forceinline__ int swz(int o) { return o ^ ((o >> 3) & 0x70); }
template<bool BF>
__device__ __forceinline__ void pack8(float* v, uint4& out, bool sub) {
    unsigned short h[8];
    #pragma unroll
    for (int j = 0; j < 8; j++) {
        if (BF) {
            __nv_bfloat16 b = __float2bfloat16(v[j]);
            h[j] = __bfloat16_as_ushort(b);
            if (sub) v[j] -= __bfloat162float(b);
        } else {
            __half b = __float2half_rn(v[j]);
            h[j] = __half_as_ushort(b);
            if (sub) v[j] -= __half2float(b);
        }
    }
    out.x = h[0] | ((uint32_t)h[1] << 16);
    out.y = h[2] | ((uint32_t)h[3] << 16);
    out.z = h[4] | ((uint32_t)h[5] << 16);
    out.w = h[6] | ((uint32_t)h[7] << 16);
}

// ---------------- universal 16-bit mma.sync GEMM ----------------
// A: 16-bit in gmem (raw copy to smem). B: fp32 in gmem, split to NBS planes in loader.
// ID 0 (f16):  g_xn  @ w1^T  + b1, relu -> g_h (half)      (B 1 plane, 1 pass)
// ID 1 (f16):  g_h   @ w2^T  + b2 + x  -> out (fp32)       (B 1 plane, 1 pass)
// ID 2 (bf16): s1t[t] @ cw1^T + cb1    -> g_y1[t] (ld 256) (B 3-split, 3 passes; feeds LIF)
// ID 3 (bf16): s2t[t] @ cw2^T + cb2    -> g_y2[t] (ld 1024)(B 2-split, 2 passes)
template<int ID>
__global__ void __launch_bounds__(256)
gemm_mma(const float* __restrict__ Bfp, const float* __restrict__ bias,
         const float* __restrict__ X, float* __restrict__ outp) {
    constexpr bool BF = (ID >= 2);
    constexpr int K   = (ID == 2) ? 1024 : 256;
    constexpr int NBS = (ID < 2) ? 1 : (ID == 2) ? 3 : 2;
    constexpr int LDC = (ID == 3) ? 1024 : 256;
    constexpr int NC  = K / 32;
    constexpr int PL  = 8192;
    constexpr int BUF = (1 + NBS) * PL;
    extern __shared__ uint8_t smp[];
    const uint32_t sbase = smem_u32(smp);

    const int tid = threadIdx.x, lane = tid & 31, wid = tid >> 5;
    const int wm = wid >> 1, wn = wid & 1;
    const int lr = lane & 15, lc = (lane >> 4) << 4;
    const int m0 = blockIdx.x * 128;
    const int n0 = blockIdx.y * 128;
    const int z  = blockIdx.z;

    const uint16_t* A =
        (ID == 0) ? (const uint16_t*)g_xn + (size_t)m0 * K :
        (ID == 1) ? (const uint16_t*)g_h  + (size_t)m0 * K :
        (ID == 2) ? (const uint16_t*)g_s1t + (size_t)z * (B_ * C_) :
                    (const uint16_t*)g_s2t + (size_t)z * (B_ * D_);
    const float* Bsrc = Bfp + (size_t)n0 * K;
    float* outb =
        (ID == 1) ? outp :
        (ID == 2) ? g_y1 + (size_t)z * (B_ * 256) :
        (ID == 3) ? g_y2 + (size_t)z * (B_ * 1024) : nullptr;

    const int sr = tid >> 1, sc = (tid & 1) * 16;
    uint4 sav0, sav1;
    float sbf[16];
    float acc[2][8][4] = {};

    auto LDG = [&](int kc) {
        const uint16_t* ap = A + (size_t)sr * K + kc + sc;
        sav0 = *(const uint4*)ap;
        sav1 = *(const uint4*)(ap + 8);
        const float* bp = Bsrc + (size_t)sr * K + kc + sc;
        #pragma unroll
        for (int q = 0; q < 4; q++) *(float4*)(sbf + 4 * q) = *(const float4*)(bp + 4 * q);
    };
    auto STS = [&](int buf) {
        uint8_t* st = smp + buf * BUF;
        const int raw = sr * 64 + sc * 2;
        const int o0 = swz(raw), o1 = swz(raw + 16);
        *(uint4*)(st + o0) = sav0;
        *(uint4*)(st + o1) = sav1;
        #pragma unroll
        for (int s = 0; s < NBS; s++) {
            uint4 u0, u1;
            pack8<BF>(sbf,     u0, s + 1 < NBS);
            pack8<BF>(sbf + 8, u1, s + 1 < NBS);
            *(uint4*)(st + (1 + s) * PL + o0) = u0;
            *(uint4*)(st + (1 + s) * PL + o1) = u1;
        }
    };
    auto MMA = [&](int buf) {
        const uint32_t bs = sbase + buf * BUF;
        #pragma unroll
        for (int p = 0; p < NBS; p++) {
            const uint32_t Ab = bs;
            const uint32_t Bb = bs + (1 + p) * PL;
            #pragma unroll
            for (int ks = 0; ks < 2; ks++) {
                uint32_t a[2][4], bq[8][2];
                #pragma unroll
                for (int mi = 0; mi < 2; mi++) {
                    int raw = (wm * 32 + mi * 16 + lr) * 64 + ks * 32 + lc;
                    ldm4(a[mi], Ab + swz(raw));
                }
                #pragma unroll
                for (int nj = 0; nj < 4; nj++) {
                    int raw = (wn * 64 + nj * 16 + lr) * 64 + ks * 32 + lc;
                    uint32_t tq[4];
                    ldm4(tq, Bb + swz(raw));
                    bq[2*nj][0] = tq[0];   bq[2*nj][1] = tq[2];
                    bq[2*nj+1][0] = tq[1]; bq[2*nj+1][1] = tq[3];
                }
                #pragma unroll
                for (int mi = 0; mi < 2; mi++)
                    #pragma unroll
                    for (int nj = 0; nj < 8; nj++)
                        mma16816<BF>(acc[mi][nj], a[mi], bq[nj]);
            }
        }
    };

    LDG(0); STS(0); __syncthreads();
    for (int i = 0; i < NC; i++) {
        if (i + 1 < NC) LDG((i + 1) * 32);
        MMA(i & 1);
        if (i + 1 < NC) STS((i + 1) & 1);
        __syncthreads();
    }

    const int er = lane >> 2, ec = (lane & 3) * 2;
    #pragma unroll
    for (int mi = 0; mi < 2; mi++) {
        #pragma unroll
        for (int nj = 0; nj < 8; nj++) {
            float* c = acc[mi][nj];
            int m = m0 + wm * 32 + mi * 16 + er;
            int n = n0 + wn * 64 + nj * 8 + ec;
            float b0 = __ldg(bias + n), b1 = __ldg(bias + n + 1);
            if (ID == 0) {
                *(__half2*)(g_h + (size_t)m * 256 + n) =
                    __floats2half2_rn(fmaxf(c[0] + b0, 0.f), fmaxf(c[1] + b1, 0.f));
                *(__half2*)(g_h + (size_t)(m + 8) * 256 + n) =
                    __floats2half2_rn(fmaxf(c[2] + b0, 0.f), fmaxf(c[3] + b1, 0.f));
            } else if (ID == 1) {
                const float* x0 = X + (size_t)m * 256 + n;
                const float* x1 = X + (size_t)(m + 8) * 256 + n;
                *(float2*)(outb + (size_t)m * LDC + n) =
                    make_float2(c[0] + x0[0] + b0, c[1] + x0[1] + b1);
                *(float2*)(outb + (size_t)(m + 8) * LDC + n) =
                    make_float2(c[2] + x1[0] + b0, c[3] + x1[1] + b1);
            } else {
                *(float2*)(outb + (size_t)m * LDC + n) = make_float2(c[0] + b0, c[1] + b1);
                *(float2*)(outb + (size_t)(m + 8) * LDC + n) = make_float2(c[2] + b0, c[3] + b1);
            }
        }
    }
}

// ---------------- LayerNorm -> fp16 g_xn ----------------
__global__ void ln_kernel(const float* __restrict__ x, const float* __restrict__ gam,
                          const float* __restrict__ bet) {
    int gw = (blockIdx.x * blockDim.x + threadIdx.x) >> 5;
    int lane = threadIdx.x & 31;
    if (gw >= ROWS) return;
    const float4* xr = (const float4*)(x + (size_t)gw * D_);
    float4 v0 = xr[lane], v1 = xr[lane + 32];
    float s = v0.x+v0.y+v0.z+v0.w + v1.x+v1.y+v1.z+v1.w;
    float q = v0.x*v0.x+v0.y*v0.y+v0.z*v0.z+v0.w*v0.w + v1.x*v1.x+v1.y*v1.y+v1.z*v1.z+v1.w*v1.w;
    #pragma unroll
    for (int o = 16; o; o >>= 1) {
        s += __shfl_xor_sync(0xffffffffu, s, o);
        q += __shfl_xor_sync(0xffffffffu, q, o);
    }
    float mu = s * (1.0f / D_);
    float rs = rsqrtf(q * (1.0f / D_) - mu * mu + 1e-5f);
    const float4* gg = (const float4*)gam;
    const float4* bb = (const float4*)bet;
    float4 g0 = gg[lane], g1 = gg[lane + 32], b0 = bb[lane], b1 = bb[lane + 32];
    __half2 h0 = __floats2half2_rn((v0.x-mu)*rs*g0.x+b0.x, (v0.y-mu)*rs*g0.y+b0.y);
    __half2 h1 = __floats2half2_rn((v0.z-mu)*rs*g0.z+b0.z, (v0.w-mu)*rs*g0.w+b0.w);
    __half2 h2 = __floats2half2_rn((v1.x-mu)*rs*g1.x+b1.x, (v1.y-mu)*rs*g1.y+b1.y);
    __half2 h3 = __floats2half2_rn((v1.z-mu)*rs*g1.z+b1.z, (v1.w-mu)*rs*g1.w+b1.w);
    __half2* base = (__half2*)(g_xn + (size_t)gw * D_);
    base[2*lane] = h0; base[2*lane+1] = h1;
    base[2*(lane+32)] = h2; base[2*(lane+32)+1] = h3;
}

// ---------------- LIF 1: x[b][c][t] -> s1t[t][b][c] bf16 ----------------
__global__ void lif1_kernel(const float* __restrict__ x) {
    int tid = blockIdx.x * blockDim.x + threadIdx.x;   // 131072
    int b = tid >> 10, c = tid & 1023;
    const float4* xr = (const float4*)(x + ((size_t)b * C_ + c) * D_);
    __nv_bfloat16* sp = g_s1t + (size_t)b * C_ + c;
    float v = 0.0f;
    for (int q = 0; q < 64; q++) {
        float4 xv = xr[q];
        float xa[4] = {xv.x, xv.y, xv.z, xv.w};
        #pragma unroll
        for (int j = 0; j < 4; j++) {
            v = v + (xa[j] - v) * 0.5f;
            float s = (v >= 1.0f) ? 1.0f : 0.0f;
            sp[(size_t)(q * 4 + j) * CB] = __float2bfloat16(s);
            if (v >= 1.0f) v = 0.0f;
        }
    }
}

// ---------------- BN stats: stage 1 (per-t slab partials) ----------------
template<int M>
__global__ void bn_slab() {
    const float* Y = (M == 256) ? g_y1 : g_y2;
    int t = blockIdx.x, tid = threadIdx.x;
    constexpr int R = M / 256;
    float s[R], q[R];
    #pragma unroll
    for (int r = 0; r < R; r++) { s[r] = 0.0f; q[r] = 0.0f; }
    const float* base = Y + (size_t)t * 128 * M;
    for (int b = 0; b < 128; b++) {
        const float* row = base + (size_t)b * M;
        #pragma unroll
        for (int r = 0; r < R; r++) {
            float v = row[tid + r * 256];
            s[r] += v; q[r] += v * v;
        }
    }
    #pragma unroll
    for (int r = 0; r < R; r++) {
        g_pS[(size_t)t * M + tid + r * 256] = s[r];
        g_pQ[(size_t)t * M + tid + r * 256] = q[r];
    }
}

// ---------------- BN stats: stage 2 ----------------
template<int M>
__global__ void bn_reduce() {
    int c = blockIdx.x * 256 + threadIdx.x;
    float S = 0.0f, Q = 0.0f;
    for (int t = 0; t < 256; t++) {
        S += g_pS[(size_t)t * M + c];
        Q += g_pQ[(size_t)t * M + c];
    }
    float mean = S * (1.0f / 32768.0f);
    float var = Q * (1.0f / 32768.0f) - mean * mean;
    float rs = rsqrtf(var + 1e-5f);
    if (M == 256) { g_mu1[c] = mean; g_rs1[c] = rs; }
    else          { g_mu2[c] = mean; g_rs2[c] = rs; }
}

// ---------------- BN1 + LIF 2: y1[t][b][o] -> s2t[t][b][o] bf16 ----------------
__global__ void lif2_kernel(const float* __restrict__ gam, const float* __restrict__ bet) {
    int tid = blockIdx.x * blockDim.x + threadIdx.x;   // 32768
    int b = tid >> 8, o = tid & 255;
    float mu = g_mu1[o], rs = g_rs1[o], ga = gam[o], be = bet[o];
    const float* yp = g_y1 + (size_t)b * 256 + o;
    __nv_bfloat16* sp = g_s2t + (size_t)b * 256 + o;
    float v = 0.0f;
    for (int t = 0; t < D_; t++) {
        float yn = ((yp[(size_t)t * 32768] - mu) * rs) * ga + be;
        v = v + (yn - v) * 0.5f;
        float s = (v >= 1.0f) ? 1.0f : 0.0f;
        sp[(size_t)t * 32768] = __float2bfloat16(s);
        if (v >= 1.0f) v = 0.0f;
    }
}

// ---------------- BN2 + transpose(t,c) + accumulate into out[b][c][t] ----------------
__global__ void final_kernel(float* __restrict__ out, const float* __restrict__ gam,
                             const float* __restrict__ bet) {
    __shared__ float tile[32][33];
    int b = blockIdx.x;
    int c0 = blockIdx.y << 5, t0 = blockIdx.z << 5;
    #pragma unroll
    for (int i = 0; i < 4; i++) {
        int t = t0 + threadIdx.y + i * 8;
        tile[threadIdx.y + i * 8][threadIdx.x] =
            g_y2[(size_t)t * (B_ * 1024) + (size_t)b * 1024 + c0 + threadIdx.x];
    }
    __syncthreads();
    #pragma unroll
    for (int i = 0; i < 4; i++) {
        int c = c0 + threadIdx.y + i * 8;
        float mu = g_mu2[c], rs = g_rs2[c], ga = __ldg(gam + c), be = __ldg(bet + c);
        size_t o = (size_t)b * (C_ * D_) + (size_t)c * D_ + t0 + threadIdx.x;
        out[o] += (tile[threadIdx.x][threadIdx.y + i * 8] - mu) * rs * ga + be;
    }
}

// ---------------- launch ----------------
extern "C" void kernel_launch(void* const* d_in, const int* in_sizes, int n_in,
                              void* d_out, int out_size) {
    const float* x    = (const float*)d_in[0];
    const float* ln_g = (const float*)d_in[1];
    const float* ln_b = (const float*)d_in[2];
    const float* w1   = (const float*)d_in[3];
    const float* b1   = (const float*)d_in[4];
    const float* w2   = (const float*)d_in[5];
    const float* b2   = (const float*)d_in[6];
    const float* cw1  = (const float*)d_in[7];
    const float* cb1  = (const float*)d_in[8];
    const float* bn1g = (const float*)d_in[9];
    const float* bn1b = (const float*)d_in[10];
    const float* cw2  = (const float*)d_in[11];
    const float* cb2  = (const float*)d_in[12];
    const float* bn2g = (const float*)d_in[13];
    const float* bn2b = (const float*)d_in[14];
    float* out = (float*)d_out;
    (void)in_sizes; (void)n_in; (void)out_size;

    const int sm2 = 2 * 2 * 8192;   // 32768 (IDs 0,1)
    const int sm4 = 2 * 4 * 8192;   // 65536 (ID 2)
    const int sm3 = 2 * 3 * 8192;   // 49152 (ID 3)
    cudaFuncSetAttribute(gemm_mma<0>, cudaFuncAttributeMaxDynamicSharedMemorySize, sm2);
    cudaFuncSetAttribute(gemm_mma<1>, cudaFuncAttributeMaxDynamicSharedMemorySize, sm2);
    cudaFuncSetAttribute(gemm_mma<2>, cudaFuncAttributeMaxDynamicSharedMemorySize, sm4);
    cudaFuncSetAttribute(gemm_mma<3>, cudaFuncAttributeMaxDynamicSharedMemorySize, sm3);

    // Mix branch (single-pass fp16)
    ln_kernel<<<ROWS / 8, 256>>>(x, ln_g, ln_b);
    gemm_mma<0><<<dim3(1024, 2), 256, sm2>>>(w1, b1, nullptr, nullptr);
    gemm_mma<1><<<dim3(1024, 2), 256, sm2>>>(w2, b2, x, out);

    // Spiking branch (bf16: spikes exact; cw1 3-split, cw2 2-split — never subnormal)
    lif1_kernel<<<CB / 256, 256>>>(x);
    gemm_mma<2><<<dim3(1, 2, 256), 256, sm4>>>(cw1, cb1, nullptr, nullptr);
    bn_slab<256><<<256, 256>>>();
    bn_reduce<256><<<1, 256>>>();
    lif2_kernel<<<128, 256>>>(bn1g, bn1b);
    gemm_mma<3><<<dim3(1, 8, 256), 256, sm3>>>(cw2, cb2, nullptr, nullptr);
    bn_slab<1024><<<256, 256>>>();
    bn_reduce<1024><<<4, 256>>>();
    final_kernel<<<dim3(B_, C_ / 32, D_ / 32), dim3(32, 8)>>>(out, bn2g, bn2b);
}

// round 11
// speedup vs baseline: 2.3807x; 1.2889x over previous
#include <cuda_runtime.h>
#include <cuda_fp16.h>
#include <cuda_bf16.h>
#include <cstdint>

#define B_ 128
#define C_ 1024
#define D_ 256
#define ROWS (B_*C_)
#define CB (C_*B_)

// ---------------- scratch ----------------
__device__ __align__(256) __half g_xn[ROWS*D_];
__device__ __align__(256) __half g_h [ROWS*D_];
__device__ __align__(256) __nv_bfloat16 g_s1t[D_*B_*C_];   // spikes1 [t][b][c]
__device__ __align__(256) __nv_bfloat16 g_s2t[D_*B_*D_];   // spikes2 [t][b][o]
__device__ float g_y1 [D_*B_*D_];
__device__ float g_y2 [D_*B_*C_];
__device__ float g_pS[D_*C_], g_pQ[D_*C_];
__device__ float g_mu1[D_], g_rs1[D_], g_mu2[C_], g_rs2[C_];
// pre-split weight planes (16-bit)
__device__ __align__(256) uint16_t g_w1h [D_*D_];          // fp16, 1 plane
__device__ __align__(256) uint16_t g_w2h [D_*D_];          // fp16, 1 plane
__device__ __align__(256) uint16_t g_cw1b[3*D_*C_];        // bf16, 3 planes
__device__ __align__(256) uint16_t g_cw2b[2*C_*D_];        // bf16, 2 planes

// ---------------- helpers ----------------
__device__ __forceinline__ uint32_t smem_u32(const void* p) {
    uint32_t a;
    asm("{ .reg .u64 t; cvta.to.shared.u64 t, %1; cvt.u32.u64 %0, t; }" : "=r"(a) : "l"(p));
    return a;
}
__device__ __forceinline__ void ldm4(uint32_t* r, uint32_t a) {
    asm volatile("ldmatrix.sync.aligned.m8n8.x4.shared.b16 {%0,%1,%2,%3}, [%4];"
        : "=r"(r[0]), "=r"(r[1]), "=r"(r[2]), "=r"(r[3]) : "r"(a));
}
template<bool BF>
__device__ __forceinline__ void mma16816(float* c, const uint32_t* a, const uint32_t* b) {
    if (BF)
        asm volatile("mma.sync.aligned.m16n8k16.row.col.f32.bf16.bf16.f32 "
            "{%0,%1,%2,%3},{%4,%5,%6,%7},{%8,%9},{%0,%1,%2,%3};"
            : "+f"(c[0]), "+f"(c[1]), "+f"(c[2]), "+f"(c[3])
            : "r"(a[0]), "r"(a[1]), "r"(a[2]), "r"(a[3]), "r"(b[0]), "r"(b[1]));
    else
        asm volatile("mma.sync.aligned.m16n8k16.row.col.f32.f16.f16.f32 "
            "{%0,%1,%2,%3},{%4,%5,%6,%7},{%8,%9},{%0,%1,%2,%3};"
            : "+f"(c[0]), "+f"(c[1]), "+f"(c[2]), "+f"(c[3])
            : "r"(a[0]), "r"(a[1]), "r"(a[2]), "r"(a[3]), "r"(b[0]), "r"(b[1]));
}
__device__ __forceinline__ int swz(int o) { return o ^ ((o >> 3) & 0x70); }
__device__ __forceinline__ void cpa16(uint32_t s, const void* g) {
    asm volatile("cp.async.cg.shared.global [%0], [%1], 16;" :: "r"(s), "l"(g));
}
#define CP_COMMIT() asm volatile("cp.async.commit_group;" ::: "memory")
#define CP_WAIT(n)  asm volatile("cp.async.wait_group %0;" :: "n"(n) : "memory")

// ---------------- weight pre-split ----------------
template<bool BF, int NBS>
__global__ void split_w(const float* __restrict__ src, uint16_t* __restrict__ dst, int n) {
    int i = blockIdx.x * 256 + threadIdx.x;
    if (i >= n) return;
    float v = src[i];
    #pragma unroll
    for (int s = 0; s < NBS; s++) {
        if (BF) {
            __nv_bfloat16 b = __float2bfloat16(v);
            dst[s * n + i] = __bfloat16_as_ushort(b);
            v -= __bfloat162float(b);
        } else {
            __half b = __float2half_rn(v);
            dst[s * n + i] = __half_as_ushort(b);
            v -= __half2float(b);
        }
    }
}

// ---------------- universal 16-bit mma.sync GEMM (cp.async 4-stage) ----------------
// A & B both 16-bit in gmem. B has NBS pre-split planes (stride NPLK).
// ID 0 (f16):  g_xn  @ w1planes  + b1, relu -> g_h (half)
// ID 1 (f16):  g_h   @ w2planes  + b2 + x  -> out (fp32)
// ID 2 (bf16): s1t[z] @ cw1planes(3) + cb1 -> g_y1[z] (ld 256)
// ID 3 (bf16): s2t[z] @ cw2planes(2) + cb2 -> g_y2[z] (ld 1024)
template<int ID>
__global__ void __launch_bounds__(256)
gemm_mma(const uint16_t* __restrict__ Bw, const float* __restrict__ bias,
         const float* __restrict__ X, float* __restrict__ outp) {
    constexpr bool BF  = (ID >= 2);
    constexpr int K    = (ID == 2) ? 1024 : 256;
    constexpr int NBS  = (ID < 2) ? 1 : (ID == 2) ? 3 : 2;
    constexpr int NPLK = (ID < 2) ? D_*D_ : (ID == 2) ? D_*C_ : C_*D_;
    constexpr int LDC  = (ID == 3) ? 1024 : 256;
    constexpr int NC   = K / 32;
    constexpr int PL   = 8192;
    constexpr int STG  = (1 + NBS) * PL;
    constexpr int S    = 4;
    extern __shared__ uint8_t smp[];
    const uint32_t sbase = smem_u32(smp);

    const int tid = threadIdx.x, lane = tid & 31, wid = tid >> 5;
    const int wm = wid >> 1, wn = wid & 1;
    const int lr = lane & 15, lc = (lane >> 4) << 4;
    const int m0 = blockIdx.x * 128;
    const int n0 = blockIdx.y * 128;
    const int z  = blockIdx.z;

    const uint16_t* A =
        (ID == 0) ? (const uint16_t*)g_xn + (size_t)m0 * K :
        (ID == 1) ? (const uint16_t*)g_h  + (size_t)m0 * K :
        (ID == 2) ? (const uint16_t*)g_s1t + (size_t)z * (B_ * C_) :
                    (const uint16_t*)g_s2t + (size_t)z * (B_ * D_);
    float* outb =
        (ID == 1) ? outp :
        (ID == 2) ? g_y1 + (size_t)z * (B_ * 256) :
        (ID == 3) ? g_y2 + (size_t)z * (B_ * 1024) : nullptr;

    const int sr = tid >> 1;                 // 0..127
    const int sc = (tid & 1) * 16;           // halves
    const int raw = sr * 64 + sc * 2;
    const int o0 = swz(raw), o1 = swz(raw + 16);
    float acc[2][8][4] = {};

    auto ISSUE = [&](int ch) {
        const uint32_t st = sbase + (ch % S) * STG;
        const uint16_t* ap = A + (size_t)sr * K + ch * 32 + sc;
        cpa16(st + o0, ap);
        cpa16(st + o1, ap + 8);
        #pragma unroll
        for (int s = 0; s < NBS; s++) {
            const uint16_t* bp = Bw + (size_t)s * NPLK + (size_t)(n0 + sr) * K + ch * 32 + sc;
            cpa16(st + (1 + s) * PL + o0, bp);
            cpa16(st + (1 + s) * PL + o1, bp + 8);
        }
    };
    auto MMA = [&](int buf) {
        const uint32_t bs = sbase + buf * STG;
        #pragma unroll
        for (int ks = 0; ks < 2; ks++) {
            uint32_t a[2][4];
            #pragma unroll
            for (int mi = 0; mi < 2; mi++) {
                int r = (wm * 32 + mi * 16 + lr) * 64 + ks * 32 + lc;
                ldm4(a[mi], bs + swz(r));
            }
            #pragma unroll
            for (int p = 0; p < NBS; p++) {
                const uint32_t Bb = bs + (1 + p) * PL;
                uint32_t bq[8][2];
                #pragma unroll
                for (int nj = 0; nj < 4; nj++) {
                    int r = (wn * 64 + nj * 16 + lr) * 64 + ks * 32 + lc;
                    uint32_t tq[4];
                    ldm4(tq, Bb + swz(r));
                    bq[2*nj][0] = tq[0];   bq[2*nj][1] = tq[2];
                    bq[2*nj+1][0] = tq[1]; bq[2*nj+1][1] = tq[3];
                }
                #pragma unroll
                for (int mi = 0; mi < 2; mi++)
                    #pragma unroll
                    for (int nj = 0; nj < 8; nj++)
                        mma16816<BF>(acc[mi][nj], a[mi], bq[nj]);
            }
        }
    };

    #pragma unroll
    for (int s = 0; s < S - 1; s++) { ISSUE(s); CP_COMMIT(); }
    for (int i = 0; i < NC; i++) {
        CP_WAIT(S - 2);
        __syncthreads();
        int nx = i + S - 1;
        if (nx < NC) ISSUE(nx);
        CP_COMMIT();
        MMA(i % S);
    }

    const int er = lane >> 2, ec = (lane & 3) * 2;
    #pragma unroll
    for (int mi = 0; mi < 2; mi++) {
        #pragma unroll
        for (int nj = 0; nj < 8; nj++) {
            float* c = acc[mi][nj];
            int m = m0 + wm * 32 + mi * 16 + er;
            int n = n0 + wn * 64 + nj * 8 + ec;
            float b0 = __ldg(bias + n), b1 = __ldg(bias + n + 1);
            if (ID == 0) {
                *(__half2*)(g_h + (size_t)m * 256 + n) =
                    __floats2half2_rn(fmaxf(c[0] + b0, 0.f), fmaxf(c[1] + b1, 0.f));
                *(__half2*)(g_h + (size_t)(m + 8) * 256 + n) =
                    __floats2half2_rn(fmaxf(c[2] + b0, 0.f), fmaxf(c[3] + b1, 0.f));
            } else if (ID == 1) {
                const float* x0 = X + (size_t)m * 256 + n;
                const float* x1 = X + (size_t)(m + 8) * 256 + n;
                *(float2*)(outb + (size_t)m * LDC + n) =
                    make_float2(c[0] + x0[0] + b0, c[1] + x0[1] + b1);
                *(float2*)(outb + (size_t)(m + 8) * LDC + n) =
                    make_float2(c[2] + x1[0] + b0, c[3] + x1[1] + b1);
            } else {
                *(float2*)(outb + (size_t)m * LDC + n) = make_float2(c[0] + b0, c[1] + b1);
                *(float2*)(outb + (size_t)(m + 8) * LDC + n) = make_float2(c[2] + b0, c[3] + b1);
            }
        }
    }
}

// ---------------- LayerNorm -> fp16 g_xn ----------------
__global__ void ln_kernel(const float* __restrict__ x, const float* __restrict__ gam,
                          const float* __restrict__ bet) {
    int gw = (blockIdx.x * blockDim.x + threadIdx.x) >> 5;
    int lane = threadIdx.x & 31;
    if (gw >= ROWS) return;
    const float4* xr = (const float4*)(x + (size_t)gw * D_);
    float4 v0 = xr[lane], v1 = xr[lane + 32];
    float s = v0.x+v0.y+v0.z+v0.w + v1.x+v1.y+v1.z+v1.w;
    float q = v0.x*v0.x+v0.y*v0.y+v0.z*v0.z+v0.w*v0.w + v1.x*v1.x+v1.y*v1.y+v1.z*v1.z+v1.w*v1.w;
    #pragma unroll
    for (int o = 16; o; o >>= 1) {
        s += __shfl_xor_sync(0xffffffffu, s, o);
        q += __shfl_xor_sync(0xffffffffu, q, o);
    }
    float mu = s * (1.0f / D_);
    float rs = rsqrtf(q * (1.0f / D_) - mu * mu + 1e-5f);
    const float4* gg = (const float4*)gam;
    const float4* bb = (const float4*)bet;
    float4 g0 = gg[lane], g1 = gg[lane + 32], b0 = bb[lane], b1 = bb[lane + 32];
    __half2 h0 = __floats2half2_rn((v0.x-mu)*rs*g0.x+b0.x, (v0.y-mu)*rs*g0.y+b0.y);
    __half2 h1 = __floats2half2_rn((v0.z-mu)*rs*g0.z+b0.z, (v0.w-mu)*rs*g0.w+b0.w);
    __half2 h2 = __floats2half2_rn((v1.x-mu)*rs*g1.x+b1.x, (v1.y-mu)*rs*g1.y+b1.y);
    __half2 h3 = __floats2half2_rn((v1.z-mu)*rs*g1.z+b1.z, (v1.w-mu)*rs*g1.w+b1.w);
    __half2* base = (__half2*)(g_xn + (size_t)gw * D_);
    base[2*lane] = h0; base[2*lane+1] = h1;
    base[2*(lane+32)] = h2; base[2*(lane+32)+1] = h3;
}

// ---------------- LIF 1: x[b][c][t] -> s1t[t][b][c] bf16 ----------------
__global__ void lif1_kernel(const float* __restrict__ x) {
    int tid = blockIdx.x * blockDim.x + threadIdx.x;
    int b = tid >> 10, c = tid & 1023;
    const float4* xr = (const float4*)(x + ((size_t)b * C_ + c) * D_);
    __nv_bfloat16* sp = g_s1t + (size_t)b * C_ + c;
    float v = 0.0f;
    for (int q = 0; q < 64; q++) {
        float4 xv = xr[q];
        float xa[4] = {xv.x, xv.y, xv.z, xv.w};
        #pragma unroll
        for (int j = 0; j < 4; j++) {
            v = v + (xa[j] - v) * 0.5f;
            float s = (v >= 1.0f) ? 1.0f : 0.0f;
            sp[(size_t)(q * 4 + j) * CB] = __float2bfloat16(s);
            if (v >= 1.0f) v = 0.0f;
        }
    }
}

// ---------------- BN stats: stage 1 ----------------
template<int M>
__global__ void bn_slab() {
    const float* Y = (M == 256) ? g_y1 : g_y2;
    int t = blockIdx.x, tid = threadIdx.x;
    constexpr int R = M / 256;
    float s[R], q[R];
    #pragma unroll
    for (int r = 0; r < R; r++) { s[r] = 0.0f; q[r] = 0.0f; }
    const float* base = Y + (size_t)t * 128 * M;
    for (int b = 0; b < 128; b++) {
        const float* row = base + (size_t)b * M;
        #pragma unroll
        for (int r = 0; r < R; r++) {
            float v = row[tid + r * 256];
            s[r] += v; q[r] += v * v;
        }
    }
    #pragma unroll
    for (int r = 0; r < R; r++) {
        g_pS[(size_t)t * M + tid + r * 256] = s[r];
        g_pQ[(size_t)t * M + tid + r * 256] = q[r];
    }
}

// ---------------- BN stats: stage 2 ----------------
template<int M>
__global__ void bn_reduce() {
    int c = blockIdx.x * 256 + threadIdx.x;
    float S = 0.0f, Q = 0.0f;
    for (int t = 0; t < 256; t++) {
        S += g_pS[(size_t)t * M + c];
        Q += g_pQ[(size_t)t * M + c];
    }
    float mean = S * (1.0f / 32768.0f);
    float var = Q * (1.0f / 32768.0f) - mean * mean;
    float rs = rsqrtf(var + 1e-5f);
    if (M == 256) { g_mu1[c] = mean; g_rs1[c] = rs; }
    else          { g_mu2[c] = mean; g_rs2[c] = rs; }
}

// ---------------- BN1 + LIF 2 ----------------
__global__ void lif2_kernel(const float* __restrict__ gam, const float* __restrict__ bet) {
    int tid = blockIdx.x * blockDim.x + threadIdx.x;
    int b = tid >> 8, o = tid & 255;
    float mu = g_mu1[o], rs = g_rs1[o], ga = gam[o], be = bet[o];
    const float* yp = g_y1 + (size_t)b * 256 + o;
    __nv_bfloat16* sp = g_s2t + (size_t)b * 256 + o;
    float v = 0.0f;
    for (int t = 0; t < D_; t++) {
        float yn = ((yp[(size_t)t * 32768] - mu) * rs) * ga + be;
        v = v + (yn - v) * 0.5f;
        float s = (v >= 1.0f) ? 1.0f : 0.0f;
        sp[(size_t)t * 32768] = __float2bfloat16(s);
        if (v >= 1.0f) v = 0.0f;
    }
}

// ---------------- BN2 + transpose(t,c) + accumulate ----------------
__global__ void final_kernel(float* __restrict__ out, const float* __restrict__ gam,
                             const float* __restrict__ bet) {
    __shared__ float tile[32][33];
    int b = blockIdx.x;
    int c0 = blockIdx.y << 5, t0 = blockIdx.z << 5;
    #pragma unroll
    for (int i = 0; i < 4; i++) {
        int t = t0 + threadIdx.y + i * 8;
        tile[threadIdx.y + i * 8][threadIdx.x] =
            g_y2[(size_t)t * (B_ * 1024) + (size_t)b * 1024 + c0 + threadIdx.x];
    }
    __syncthreads();
    #pragma unroll
    for (int i = 0; i < 4; i++) {
        int c = c0 + threadIdx.y + i * 8;
        float mu = g_mu2[c], rs = g_rs2[c], ga = __ldg(gam + c), be = __ldg(bet + c);
        size_t o = (size_t)b * (C_ * D_) + (size_t)c * D_ + t0 + threadIdx.x;
        out[o] += (tile[threadIdx.x][threadIdx.y + i * 8] - mu) * rs * ga + be;
    }
}

// ---------------- launch ----------------
extern "C" void kernel_launch(void* const* d_in, const int* in_sizes, int n_in,
                              void* d_out, int out_size) {
    const float* x    = (const float*)d_in[0];
    const float* ln_g = (const float*)d_in[1];
    const float* ln_b = (const float*)d_in[2];
    const float* w1   = (const float*)d_in[3];
    const float* b1   = (const float*)d_in[4];
    const float* w2   = (const float*)d_in[5];
    const float* b2   = (const float*)d_in[6];
    const float* cw1  = (const float*)d_in[7];
    const float* cb1  = (const float*)d_in[8];
    const float* bn1g = (const float*)d_in[9];
    const float* bn1b = (const float*)d_in[10];
    const float* cw2  = (const float*)d_in[11];
    const float* cb2  = (const float*)d_in[12];
    const float* bn2g = (const float*)d_in[13];
    const float* bn2b = (const float*)d_in[14];
    float* out = (float*)d_out;
    (void)in_sizes; (void)n_in; (void)out_size;

    uint16_t *dw1h, *dw2h, *dcw1b, *dcw2b;
    cudaGetSymbolAddress((void**)&dw1h, g_w1h);
    cudaGetSymbolAddress((void**)&dw2h, g_w2h);
    cudaGetSymbolAddress((void**)&dcw1b, g_cw1b);
    cudaGetSymbolAddress((void**)&dcw2b, g_cw2b);

    const int sm01 = 4 * 2 * 8192;   // 65536
    const int sm2  = 4 * 4 * 8192;   // 131072
    const int sm3  = 4 * 3 * 8192;   // 98304
    cudaFuncSetAttribute(gemm_mma<0>, cudaFuncAttributeMaxDynamicSharedMemorySize, sm01);
    cudaFuncSetAttribute(gemm_mma<1>, cudaFuncAttributeMaxDynamicSharedMemorySize, sm01);
    cudaFuncSetAttribute(gemm_mma<2>, cudaFuncAttributeMaxDynamicSharedMemorySize, sm2);
    cudaFuncSetAttribute(gemm_mma<3>, cudaFuncAttributeMaxDynamicSharedMemorySize, sm3);

    // weight pre-split (once per launch; trivial cost)
    split_w<false, 1><<<D_*D_/256, 256>>>(w1, dw1h, D_*D_);
    split_w<false, 1><<<D_*D_/256, 256>>>(w2, dw2h, D_*D_);
    split_w<true,  3><<<D_*C_/256, 256>>>(cw1, dcw1b, D_*C_);
    split_w<true,  2><<<C_*D_/256, 256>>>(cw2, dcw2b, C_*D_);

    // Mix branch
    ln_kernel<<<ROWS / 8, 256>>>(x, ln_g, ln_b);
    gemm_mma<0><<<dim3(1024, 2), 256, sm01>>>(dw1h, b1, nullptr, nullptr);
    gemm_mma<1><<<dim3(1024, 2), 256, sm01>>>(dw2h, b2, x, out);

    // Spiking branch
    lif1_kernel<<<CB / 256, 256>>>(x);
    gemm_mma<2><<<dim3(1, 2, 256), 256, sm2>>>(dcw1b, cb1, nullptr, nullptr);
    bn_slab<256><<<256, 256>>>();
    bn_reduce<256><<<1, 256>>>();
    lif2_kernel<<<128, 256>>>(bn1g, bn1b);
    gemm_mma<3><<<dim3(1, 8, 256), 256, sm3>>>(dcw2b, cb2, nullptr, nullptr);
    bn_slab<1024><<<256, 256>>>();
    bn_reduce<1024><<<4, 256>>>();
    final_kernel<<<dim3(B_, C_ / 32, D_ / 32), dim3(32, 8)>>>(out, bn2g, bn2b);
}

// round 14
// speedup vs baseline: 2.4641x; 1.0350x over previous
#include <cuda_runtime.h>
#include <cuda_fp16.h>
#include <cuda_bf16.h>
#include <cstdint>

#define B_ 128
#define C_ 1024
#define D_ 256
#define ROWS (B_*C_)
#define CB (C_*B_)

// ---------------- scratch ----------------
__device__ __align__(256) __half g_xn[ROWS*D_];
__device__ __align__(256) __half g_h [ROWS*D_];
__device__ __align__(256) __nv_bfloat16 g_s1t[D_*B_*C_];   // spikes1 [t][b][c]
__device__ __align__(256) __nv_bfloat16 g_s2t[D_*B_*D_];   // spikes2 [t][b][o]
__device__ float g_y1 [D_*B_*D_];
__device__ float g_y2 [D_*B_*C_];
__device__ float g_pS[D_*D_], g_pQ[D_*D_];                 // BN1 two-stage partials
__device__ float g_S2[C_], g_Q2[C_];                       // BN2 fused stats
__device__ float g_mu1[D_], g_rs1[D_], g_mu2[C_], g_rs2[C_];
// pre-split weight planes (16-bit)
__device__ __align__(256) uint16_t g_w1h [D_*D_];          // fp16, 1 plane
__device__ __align__(256) uint16_t g_w2h [D_*D_];          // fp16, 1 plane
__device__ __align__(256) uint16_t g_cw1b[3*D_*C_];        // bf16, 3 planes (threshold-critical)
__device__ __align__(256) uint16_t g_cw2b[2*C_*D_];        // bf16, 2 planes

// ---------------- helpers ----------------
__device__ __forceinline__ uint32_t smem_u32(const void* p) {
    uint32_t a;
    asm("{ .reg .u64 t; cvta.to.shared.u64 t, %1; cvt.u32.u64 %0, t; }" : "=r"(a) : "l"(p));
    return a;
}
__device__ __forceinline__ void ldm4(uint32_t* r, uint32_t a) {
    asm volatile("ldmatrix.sync.aligned.m8n8.x4.shared.b16 {%0,%1,%2,%3}, [%4];"
        : "=r"(r[0]), "=r"(r[1]), "=r"(r[2]), "=r"(r[3]) : "r"(a));
}
template<bool BF>
__device__ __forceinline__ void mma16816(float* c, const uint32_t* a, const uint32_t* b) {
    if (BF)
        asm volatile("mma.sync.aligned.m16n8k16.row.col.f32.bf16.bf16.f32 "
            "{%0,%1,%2,%3},{%4,%5,%6,%7},{%8,%9},{%0,%1,%2,%3};"
            : "+f"(c[0]), "+f"(c[1]), "+f"(c[2]), "+f"(c[3])
            : "r"(a[0]), "r"(a[1]), "r"(a[2]), "r"(a[3]), "r"(b[0]), "r"(b[1]));
    else
        asm volatile("mma.sync.aligned.m16n8k16.row.col.f32.f16.f16.f32 "
            "{%0,%1,%2,%3},{%4,%5,%6,%7},{%8,%9},{%0,%1,%2,%3};"
            : "+f"(c[0]), "+f"(c[1]), "+f"(c[2]), "+f"(c[3])
            : "r"(a[0]), "r"(a[1]), "r"(a[2]), "r"(a[3]), "r"(b[0]), "r"(b[1]));
}
__device__ __forceinline__ int swz(int o) { return o ^ ((o >> 3) & 0x70); }
__device__ __forceinline__ void cpa16(uint32_t s, const void* g) {
    asm volatile("cp.async.cg.shared.global [%0], [%1], 16;" :: "r"(s), "l"(g));
}
#define CP_COMMIT() asm volatile("cp.async.commit_group;" ::: "memory")
#define CP_WAIT(n)  asm volatile("cp.async.wait_group %0;" :: "n"(n) : "memory")

// ---------------- weight pre-split ----------------
template<bool BF, int NBS>
__global__ void split_w(const float* __restrict__ src, uint16_t* __restrict__ dst, int n) {
    int i = blockIdx.x * 256 + threadIdx.x;
    if (i >= n) return;
    float v = src[i];
    #pragma unroll
    for (int s = 0; s < NBS; s++) {
        if (BF) {
            __nv_bfloat16 b = __float2bfloat16(v);
            dst[s * n + i] = __bfloat16_as_ushort(b);
            v -= __bfloat162float(b);
        } else {
            __half b = __float2half_rn(v);
            dst[s * n + i] = __half_as_ushort(b);
            v -= __half2float(b);
        }
    }
}

// ---------------- BN2 fused-stat helpers ----------------
__global__ void zero_stats2() {
    int i = blockIdx.x * 256 + threadIdx.x;
    if (i < C_) { g_S2[i] = 0.f; g_Q2[i] = 0.f; }
}
__global__ void bn_fin2() {
    int c = blockIdx.x * 256 + threadIdx.x;
    float mean = g_S2[c] * (1.0f / 32768.0f);
    float var = g_Q2[c] * (1.0f / 32768.0f) - mean * mean;
    g_mu2[c] = mean;
    g_rs2[c] = rsqrtf(var + 1e-5f);
}

// ---------------- BN1 two-stage stats (proven, threshold-critical) ----------------
__global__ void bn_slab1() {
    int t = blockIdx.x, tid = threadIdx.x;
    float s = 0.0f, q = 0.0f;
    const float* base = g_y1 + (size_t)t * 128 * 256;
    for (int b = 0; b < 128; b++) {
        float v = base[(size_t)b * 256 + tid];
        s += v; q += v * v;
    }
    g_pS[(size_t)t * 256 + tid] = s;
    g_pQ[(size_t)t * 256 + tid] = q;
}
__global__ void bn_reduce1() {
    int c = blockIdx.x * 256 + threadIdx.x;
    float S = 0.0f, Q = 0.0f;
    for (int t = 0; t < 256; t++) {
        S += g_pS[(size_t)t * 256 + c];
        Q += g_pQ[(size_t)t * 256 + c];
    }
    float mean = S * (1.0f / 32768.0f);
    float var = Q * (1.0f / 32768.0f) - mean * mean;
    g_mu1[c] = mean;
    g_rs1[c] = rsqrtf(var + 1e-5f);
}

// ---------------- universal 16-bit mma.sync GEMM (cp.async 4-stage) ----------------
// ID 0 (f16):  g_xn  @ w1(1 plane)  + b1, relu -> g_h (half)
// ID 1 (f16):  g_h   @ w2(1 plane)  + b2 + x  -> out (fp32)
// ID 2 (bf16): s1t[z] @ cw1(3 planes) + cb1 -> g_y1[z] (ld 256)   [stats via two-stage kernels]
// ID 3 (bf16): s2t[z] @ cw2(2 planes) + cb2 -> g_y2[z] (ld 1024) + fused BN2 stats
template<int ID>
__global__ void __launch_bounds__(256)
gemm_mma(const uint16_t* __restrict__ Bw, const float* __restrict__ bias,
         const float* __restrict__ X, float* __restrict__ outp) {
    constexpr bool BF  = (ID >= 2);
    constexpr int K    = (ID == 2) ? 1024 : 256;
    constexpr int NBS  = (ID < 2) ? 1 : (ID == 2) ? 3 : 2;
    constexpr int NPLK = (ID < 2) ? D_*D_ : (ID == 2) ? D_*C_ : C_*D_;
    constexpr int LDC  = (ID == 3) ? 1024 : 256;
    constexpr int NC   = K / 32;
    constexpr int PL   = 8192;
    constexpr int STG  = (1 + NBS) * PL;
    constexpr int S    = 4;
    extern __shared__ uint8_t smp[];
    const uint32_t sbase = smem_u32(smp);

    const int tid = threadIdx.x, lane = tid & 31, wid = tid >> 5;
    const int wm = wid >> 1, wn = wid & 1;
    const int lr = lane & 15, lc = (lane >> 4) << 4;
    const int m0 = blockIdx.x * 128;
    const int n0 = blockIdx.y * 128;
    const int z  = blockIdx.z;

    const uint16_t* A =
        (ID == 0) ? (const uint16_t*)g_xn + (size_t)m0 * K :
        (ID == 1) ? (const uint16_t*)g_h  + (size_t)m0 * K :
        (ID == 2) ? (const uint16_t*)g_s1t + (size_t)z * (B_ * C_) :
                    (const uint16_t*)g_s2t + (size_t)z * (B_ * D_);
    float* outb =
        (ID == 1) ? outp :
        (ID == 2) ? g_y1 + (size_t)z * (B_ * 256) :
        (ID == 3) ? g_y2 + (size_t)z * (B_ * 1024) : nullptr;

    const int sr = tid >> 1;
    const int sc = (tid & 1) * 16;
    const int raw = sr * 64 + sc * 2;
    const int o0 = swz(raw), o1 = swz(raw + 16);
    float acc[2][8][4] = {};

    auto ISSUE = [&](int ch) {
        const uint32_t st = sbase + (ch % S) * STG;
        const uint16_t* ap = A + (size_t)sr * K + ch * 32 + sc;
        cpa16(st + o0, ap);
        cpa16(st + o1, ap + 8);
        #pragma unroll
        for (int s = 0; s < NBS; s++) {
            const uint16_t* bp = Bw + (size_t)s * NPLK + (size_t)(n0 + sr) * K + ch * 32 + sc;
            cpa16(st + (1 + s) * PL + o0, bp);
            cpa16(st + (1 + s) * PL + o1, bp + 8);
        }
    };
    auto MMA = [&](int buf) {
        const uint32_t bs = sbase + buf * STG;
        #pragma unroll
        for (int ks = 0; ks < 2; ks++) {
            uint32_t a[2][4];
            #pragma unroll
            for (int mi = 0; mi < 2; mi++) {
                int r = (wm * 32 + mi * 16 + lr) * 64 + ks * 32 + lc;
                ldm4(a[mi], bs + swz(r));
            }
            #pragma unroll
            for (int p = 0; p < NBS; p++) {
                const uint32_t Bb = bs + (1 + p) * PL;
                uint32_t bq[8][2];
                #pragma unroll
                for (int nj = 0; nj < 4; nj++) {
                    int r = (wn * 64 + nj * 16 + lr) * 64 + ks * 32 + lc;
                    uint32_t tq[4];
                    ldm4(tq, Bb + swz(r));
                    bq[2*nj][0] = tq[0];   bq[2*nj][1] = tq[2];
                    bq[2*nj+1][0] = tq[1]; bq[2*nj+1][1] = tq[3];
                }
                #pragma unroll
                for (int mi = 0; mi < 2; mi++)
                    #pragma unroll
                    for (int nj = 0; nj < 8; nj++)
                        mma16816<BF>(acc[mi][nj], a[mi], bq[nj]);
            }
        }
    };

    #pragma unroll
    for (int s = 0; s < S - 1; s++) { ISSUE(s); CP_COMMIT(); }
    for (int i = 0; i < NC; i++) {
        CP_WAIT(S - 2);
        __syncthreads();
        int nx = i + S - 1;
        if (nx < NC) ISSUE(nx);
        CP_COMMIT();
        MMA(i % S);
    }

    const int er = lane >> 2, ec = (lane & 3) * 2;
    #pragma unroll
    for (int mi = 0; mi < 2; mi++) {
        #pragma unroll
        for (int nj = 0; nj < 8; nj++) {
            float* c = acc[mi][nj];
            int m = m0 + wm * 32 + mi * 16 + er;
            int n = n0 + wn * 64 + nj * 8 + ec;
            float b0 = __ldg(bias + n), b1 = __ldg(bias + n + 1);
            if (ID == 0) {
                *(__half2*)(g_h + (size_t)m * 256 + n) =
                    __floats2half2_rn(fmaxf(c[0] + b0, 0.f), fmaxf(c[1] + b1, 0.f));
                *(__half2*)(g_h + (size_t)(m + 8) * 256 + n) =
                    __floats2half2_rn(fmaxf(c[2] + b0, 0.f), fmaxf(c[3] + b1, 0.f));
            } else if (ID == 1) {
                const float* x0 = X + (size_t)m * 256 + n;
                const float* x1 = X + (size_t)(m + 8) * 256 + n;
                *(float2*)(outb + (size_t)m * LDC + n) =
                    make_float2(c[0] + x0[0] + b0, c[1] + x0[1] + b1);
                *(float2*)(outb + (size_t)(m + 8) * LDC + n) =
                    make_float2(c[2] + x1[0] + b0, c[3] + x1[1] + b1);
            } else if (ID == 2) {
                *(float2*)(outb + (size_t)m * LDC + n) = make_float2(c[0] + b0, c[1] + b1);
                *(float2*)(outb + (size_t)(m + 8) * LDC + n) = make_float2(c[2] + b0, c[3] + b1);
            } else {
                float y00 = c[0] + b0, y01 = c[1] + b1;
                float y10 = c[2] + b0, y11 = c[3] + b1;
                *(float2*)(outb + (size_t)m * LDC + n) = make_float2(y00, y01);
                *(float2*)(outb + (size_t)(m + 8) * LDC + n) = make_float2(y10, y11);
                // fused BN2 stats (output-side only; NOT threshold-feeding)
                float a0 = y00 + y10, a1 = y01 + y11;
                float q0 = y00 * y00 + y10 * y10, q1 = y01 * y01 + y11 * y11;
                #pragma unroll
                for (int off = 4; off < 32; off <<= 1) {
                    a0 += __shfl_xor_sync(0xffffffffu, a0, off);
                    a1 += __shfl_xor_sync(0xffffffffu, a1, off);
                    q0 += __shfl_xor_sync(0xffffffffu, q0, off);
                    q1 += __shfl_xor_sync(0xffffffffu, q1, off);
                }
                if (er == 0) {
                    atomicAdd(g_S2 + n, a0);
                    atomicAdd(g_S2 + n + 1, a1);
                    atomicAdd(g_Q2 + n, q0);
                    atomicAdd(g_Q2 + n + 1, q1);
                }
            }
        }
    }
}

// ---------------- LayerNorm -> fp16 g_xn ----------------
__global__ void ln_kernel(const float* __restrict__ x, const float* __restrict__ gam,
                          const float* __restrict__ bet) {
    int gw = (blockIdx.x * blockDim.x + threadIdx.x) >> 5;
    int lane = threadIdx.x & 31;
    if (gw >= ROWS) return;
    const float4* xr = (const float4*)(x + (size_t)gw * D_);
    float4 v0 = xr[lane], v1 = xr[lane + 32];
    float s = v0.x+v0.y+v0.z+v0.w + v1.x+v1.y+v1.z+v1.w;
    float q = v0.x*v0.x+v0.y*v0.y+v0.z*v0.z+v0.w*v0.w + v1.x*v1.x+v1.y*v1.y+v1.z*v1.z+v1.w*v1.w;
    #pragma unroll
    for (int o = 16; o; o >>= 1) {
        s += __shfl_xor_sync(0xffffffffu, s, o);
        q += __shfl_xor_sync(0xffffffffu, q, o);
    }
    float mu = s * (1.0f / D_);
    float rs = rsqrtf(q * (1.0f / D_) - mu * mu + 1e-5f);
    const float4* gg = (const float4*)gam;
    const float4* bb = (const float4*)bet;
    float4 g0 = gg[lane], g1 = gg[lane + 32], b0 = bb[lane], b1 = bb[lane + 32];
    __half2 h0 = __floats2half2_rn((v0.x-mu)*rs*g0.x+b0.x, (v0.y-mu)*rs*g0.y+b0.y);
    __half2 h1 = __floats2half2_rn((v0.z-mu)*rs*g0.z+b0.z, (v0.w-mu)*rs*g0.w+b0.w);
    __half2 h2 = __floats2half2_rn((v1.x-mu)*rs*g1.x+b1.x, (v1.y-mu)*rs*g1.y+b1.y);
    __half2 h3 = __floats2half2_rn((v1.z-mu)*rs*g1.z+b1.z, (v1.w-mu)*rs*g1.w+b1.w);
    __half2* base = (__half2*)(g_xn + (size_t)gw * D_);
    base[2*lane] = h0; base[2*lane+1] = h1;
    base[2*(lane+32)] = h2; base[2*(lane+32)+1] = h3;
}

// ---------------- LIF 1: x[b][c][t] -> s1t[t][b][c] bf16 ----------------
__global__ void lif1_kernel(const float* __restrict__ x) {
    int tid = blockIdx.x * blockDim.x + threadIdx.x;
    int b = tid >> 10, c = tid & 1023;
    const float4* xr = (const float4*)(x + ((size_t)b * C_ + c) * D_);
    __nv_bfloat16* sp = g_s1t + (size_t)b * C_ + c;
    float v = 0.0f;
    for (int q = 0; q < 64; q++) {
        float4 xv = xr[q];
        float xa[4] = {xv.x, xv.y, xv.z, xv.w};
        #pragma unroll
        for (int j = 0; j < 4; j++) {
            v = v + (xa[j] - v) * 0.5f;
            float s = (v >= 1.0f) ? 1.0f : 0.0f;
            sp[(size_t)(q * 4 + j) * CB] = __float2bfloat16(s);
            if (v >= 1.0f) v = 0.0f;
        }
    }
}

// ---------------- BN1 + LIF 2 ----------------
__global__ void lif2_kernel(const float* __restrict__ gam, const float* __restrict__ bet) {
    int tid = blockIdx.x * blockDim.x + threadIdx.x;
    int b = tid >> 8, o = tid & 255;
    float mu = g_mu1[o], rs = g_rs1[o], ga = gam[o], be = bet[o];
    const float* yp = g_y1 + (size_t)b * 256 + o;
    __nv_bfloat16* sp = g_s2t + (size_t)b * 256 + o;
    float v = 0.0f;
    for (int t = 0; t < D_; t++) {
        float yn = ((yp[(size_t)t * 32768] - mu) * rs) * ga + be;
        v = v + (yn - v) * 0.5f;
        float s = (v >= 1.0f) ? 1.0f : 0.0f;
        sp[(size_t)t * 32768] = __float2bfloat16(s);
        if (v >= 1.0f) v = 0.0f;
    }
}

// ---------------- BN2 + transpose(t,c) + accumulate ----------------
__global__ void final_kernel(float* __restrict__ out, const float* __restrict__ gam,
                             const float* __restrict__ bet) {
    __shared__ float tile[32][33];
    int b = blockIdx.x;
    int c0 = blockIdx.y << 5, t0 = blockIdx.z << 5;
    #pragma unroll
    for (int i = 0; i < 4; i++) {
        int t = t0 + threadIdx.y + i * 8;
        tile[threadIdx.y + i * 8][threadIdx.x] =
            g_y2[(size_t)t * (B_ * 1024) + (size_t)b * 1024 + c0 + threadIdx.x];
    }
    __syncthreads();
    #pragma unroll
    for (int i = 0; i < 4; i++) {
        int c = c0 + threadIdx.y + i * 8;
        float mu = g_mu2[c], rs = g_rs2[c], ga = __ldg(gam + c), be = __ldg(bet + c);
        size_t o = (size_t)b * (C_ * D_) + (size_t)c * D_ + t0 + threadIdx.x;
        out[o] += (tile[threadIdx.x][threadIdx.y + i * 8] - mu) * rs * ga + be;
    }
}

// ---------------- launch ----------------
extern "C" void kernel_launch(void* const* d_in, const int* in_sizes, int n_in,
                              void* d_out, int out_size) {
    const float* x    = (const float*)d_in[0];
    const float* ln_g = (const float*)d_in[1];
    const float* ln_b = (const float*)d_in[2];
    const float* w1   = (const float*)d_in[3];
    const float* b1   = (const float*)d_in[4];
    const float* w2   = (const float*)d_in[5];
    const float* b2   = (const float*)d_in[6];
    const float* cw1  = (const float*)d_in[7];
    const float* cb1  = (const float*)d_in[8];
    const float* bn1g = (const float*)d_in[9];
    const float* bn1b = (const float*)d_in[10];
    const float* cw2  = (const float*)d_in[11];
    const float* cb2  = (const float*)d_in[12];
    const float* bn2g = (const float*)d_in[13];
    const float* bn2b = (const float*)d_in[14];
    float* out = (float*)d_out;
    (void)in_sizes; (void)n_in; (void)out_size;

    uint16_t *dw1h, *dw2h, *dcw1b, *dcw2b;
    cudaGetSymbolAddress((void**)&dw1h, g_w1h);
    cudaGetSymbolAddress((void**)&dw2h, g_w2h);
    cudaGetSymbolAddress((void**)&dcw1b, g_cw1b);
    cudaGetSymbolAddress((void**)&dcw2b, g_cw2b);

    const int sm01 = 4 * 2 * 8192;   // 65536  (IDs 0,1)
    const int sm2  = 4 * 4 * 8192;   // 131072 (ID 2: 1 A + 3 B planes)
    const int sm3  = 4 * 3 * 8192;   // 98304  (ID 3)
    cudaFuncSetAttribute(gemm_mma<0>, cudaFuncAttributeMaxDynamicSharedMemorySize, sm01);
    cudaFuncSetAttribute(gemm_mma<1>, cudaFuncAttributeMaxDynamicSharedMemorySize, sm01);
    cudaFuncSetAttribute(gemm_mma<2>, cudaFuncAttributeMaxDynamicSharedMemorySize, sm2);
    cudaFuncSetAttribute(gemm_mma<3>, cudaFuncAttributeMaxDynamicSharedMemorySize, sm3);

    // prep
    split_w<false, 1><<<D_*D_/256, 256>>>(w1, dw1h, D_*D_);
    split_w<false, 1><<<D_*D_/256, 256>>>(w2, dw2h, D_*D_);
    split_w<true,  3><<<D_*C_/256, 256>>>(cw1, dcw1b, D_*C_);
    split_w<true,  2><<<C_*D_/256, 256>>>(cw2, dcw2b, C_*D_);
    zero_stats2<<<4, 256>>>();

    // Mix branch
    ln_kernel<<<ROWS / 8, 256>>>(x, ln_g, ln_b);
    gemm_mma<0><<<dim3(1024, 2), 256, sm01>>>(dw1h, b1, nullptr, nullptr);
    gemm_mma<1><<<dim3(1024, 2), 256, sm01>>>(dw2h, b2, x, out);

    // Spiking branch
    lif1_kernel<<<CB / 256, 256>>>(x);
    gemm_mma<2><<<dim3(1, 2, 256), 256, sm2>>>(dcw1b, cb1, nullptr, nullptr);
    bn_slab1<<<256, 256>>>();
    bn_reduce1<<<1, 256>>>();
    lif2_kernel<<<128, 256>>>(bn1g, bn1b);
    gemm_mma<3><<<dim3(1, 8, 256), 256, sm3>>>(dcw2b, cb2, nullptr, nullptr);
    bn_fin2<<<4, 256>>>();
    final_kernel<<<dim3(B_, C_ / 32, D_ / 32), dim3(32, 8)>>>(out, bn2g, bn2b);
}

// round 15
// speedup vs baseline: 2.8145x; 1.1422x over previous
#include <cuda_runtime.h>
#include <cuda_fp16.h>
#include <cuda_bf16.h>
#include <cstdint>

#define B_ 128
#define C_ 1024
#define D_ 256
#define ROWS (B_*C_)
#define CB (C_*B_)

// ---------------- scratch ----------------
__device__ __align__(256) __half g_xn[ROWS*D_];
__device__ __align__(256) __half g_h [ROWS*D_];
__device__ __align__(256) __nv_bfloat16 g_s1t[D_*B_*C_];   // spikes1 [t][b][c]
__device__ __align__(256) __nv_bfloat16 g_s2t[D_*B_*D_];   // spikes2 [t][b][o]
__device__ float g_y1 [D_*B_*D_];
__device__ float g_y2 [D_*B_*C_];
__device__ float g_pS[D_*D_], g_pQ[D_*D_];                 // BN1 two-stage partials
__device__ float g_S2[C_], g_Q2[C_];                       // BN2 fused stats
__device__ float g_mu1[D_], g_rs1[D_];
// pre-split weight planes (16-bit)
__device__ __align__(256) uint16_t g_w1h [D_*D_];
__device__ __align__(256) uint16_t g_w2h [D_*D_];
__device__ __align__(256) uint16_t g_cw1b[3*D_*C_];        // bf16, 3 planes (threshold-critical)
__device__ __align__(256) uint16_t g_cw2b[2*C_*D_];        // bf16, 2 planes

// ---------------- helpers ----------------
__device__ __forceinline__ uint32_t smem_u32(const void* p) {
    uint32_t a;
    asm("{ .reg .u64 t; cvta.to.shared.u64 t, %1; cvt.u32.u64 %0, t; }" : "=r"(a) : "l"(p));
    return a;
}
__device__ __forceinline__ void ldm4(uint32_t* r, uint32_t a) {
    asm volatile("ldmatrix.sync.aligned.m8n8.x4.shared.b16 {%0,%1,%2,%3}, [%4];"
        : "=r"(r[0]), "=r"(r[1]), "=r"(r[2]), "=r"(r[3]) : "r"(a));
}
template<bool BF>
__device__ __forceinline__ void mma16816(float* c, const uint32_t* a, const uint32_t* b) {
    if (BF)
        asm volatile("mma.sync.aligned.m16n8k16.row.col.f32.bf16.bf16.f32 "
            "{%0,%1,%2,%3},{%4,%5,%6,%7},{%8,%9},{%0,%1,%2,%3};"
            : "+f"(c[0]), "+f"(c[1]), "+f"(c[2]), "+f"(c[3])
            : "r"(a[0]), "r"(a[1]), "r"(a[2]), "r"(a[3]), "r"(b[0]), "r"(b[1]));
    else
        asm volatile("mma.sync.aligned.m16n8k16.row.col.f32.f16.f16.f32 "
            "{%0,%1,%2,%3},{%4,%5,%6,%7},{%8,%9},{%0,%1,%2,%3};"
            : "+f"(c[0]), "+f"(c[1]), "+f"(c[2]), "+f"(c[3])
            : "r"(a[0]), "r"(a[1]), "r"(a[2]), "r"(a[3]), "r"(b[0]), "r"(b[1]));
}
__device__ __forceinline__ int swz(int o) { return o ^ ((o >> 3) & 0x70); }
__device__ __forceinline__ void cpa16(uint32_t s, const void* g) {
    asm volatile("cp.async.cg.shared.global [%0], [%1], 16;" :: "r"(s), "l"(g));
}
#define CP_COMMIT() asm volatile("cp.async.commit_group;" ::: "memory")
#define CP_WAIT(n)  asm volatile("cp.async.wait_group %0;" :: "n"(n) : "memory")

// ---------------- GEMM core (identical arithmetic to R14) ----------------
// ID 0 (f16):  g_xn  @ w1(1 plane)  + b1, relu -> g_h (half)
// ID 1 (f16):  g_h   @ w2(1 plane)  + b2 + x  -> out (fp32)
// ID 2 (bf16): s1t[z] @ cw1(3 planes) + cb1 -> g_y1[z]    [stats via two-stage kernels]
// ID 3 (bf16): s2t[z] @ cw2(2 planes) + cb2 -> g_y2[z] + fused BN2 stats
template<int ID, int S>
__device__ __forceinline__ void gemm_core(
    int m0, int n0, int z,
    const uint16_t* __restrict__ Bw, const float* __restrict__ bias,
    const float* __restrict__ X, float* __restrict__ outp, uint8_t* smp)
{
    constexpr bool BF  = (ID >= 2);
    constexpr int K    = (ID == 2) ? 1024 : 256;
    constexpr int NBS  = (ID < 2) ? 1 : (ID == 2) ? 3 : 2;
    constexpr int NPLK = (ID < 2) ? D_*D_ : (ID == 2) ? D_*C_ : C_*D_;
    constexpr int LDC  = (ID == 3) ? 1024 : 256;
    constexpr int NC   = K / 32;
    constexpr int PL   = 8192;
    constexpr int STG  = (1 + NBS) * PL;
    const uint32_t sbase = smem_u32(smp);

    const int tid = threadIdx.x, lane = tid & 31, wid = tid >> 5;
    const int wm = wid >> 1, wn = wid & 1;
    const int lr = lane & 15, lc = (lane >> 4) << 4;

    const uint16_t* A =
        (ID == 0) ? (const uint16_t*)g_xn + (size_t)m0 * K :
        (ID == 1) ? (const uint16_t*)g_h  + (size_t)m0 * K :
        (ID == 2) ? (const uint16_t*)g_s1t + (size_t)z * (B_ * C_) :
                    (const uint16_t*)g_s2t + (size_t)z * (B_ * D_);
    float* outb =
        (ID == 1) ? outp :
        (ID == 2) ? g_y1 + (size_t)z * (B_ * 256) :
        (ID == 3) ? g_y2 + (size_t)z * (B_ * 1024) : nullptr;

    const int sr = tid >> 1;
    const int sc = (tid & 1) * 16;
    const int raw = sr * 64 + sc * 2;
    const int o0 = swz(raw), o1 = swz(raw + 16);
    float acc[2][8][4] = {};

    auto ISSUE = [&](int ch) {
        const uint32_t st = sbase + (ch % S) * STG;
        const uint16_t* ap = A + (size_t)sr * K + ch * 32 + sc;
        cpa16(st + o0, ap);
        cpa16(st + o1, ap + 8);
        #pragma unroll
        for (int s = 0; s < NBS; s++) {
            const uint16_t* bp = Bw + (size_t)s * NPLK + (size_t)(n0 + sr) * K + ch * 32 + sc;
            cpa16(st + (1 + s) * PL + o0, bp);
            cpa16(st + (1 + s) * PL + o1, bp + 8);
        }
    };
    auto MMA = [&](int buf) {
        const uint32_t bs = sbase + buf * STG;
        #pragma unroll
        for (int ks = 0; ks < 2; ks++) {
            uint32_t a[2][4];
            #pragma unroll
            for (int mi = 0; mi < 2; mi++) {
                int r = (wm * 32 + mi * 16 + lr) * 64 + ks * 32 + lc;
                ldm4(a[mi], bs + swz(r));
            }
            #pragma unroll
            for (int p = 0; p < NBS; p++) {
                const uint32_t Bb = bs + (1 + p) * PL;
                uint32_t bq[8][2];
                #pragma unroll
                for (int nj = 0; nj < 4; nj++) {
                    int r = (wn * 64 + nj * 16 + lr) * 64 + ks * 32 + lc;
                    uint32_t tq[4];
                    ldm4(tq, Bb + swz(r));
                    bq[2*nj][0] = tq[0];   bq[2*nj][1] = tq[2];
                    bq[2*nj+1][0] = tq[1]; bq[2*nj+1][1] = tq[3];
                }
                #pragma unroll
                for (int mi = 0; mi < 2; mi++)
                    #pragma unroll
                    for (int nj = 0; nj < 8; nj++)
                        mma16816<BF>(acc[mi][nj], a[mi], bq[nj]);
            }
        }
    };

    #pragma unroll
    for (int s = 0; s < S - 1; s++) { ISSUE(s); CP_COMMIT(); }
    for (int i = 0; i < NC; i++) {
        CP_WAIT(S - 2);
        __syncthreads();
        int nx = i + S - 1;
        if (nx < NC) ISSUE(nx);
        CP_COMMIT();
        MMA(i % S);
    }

    const int er = lane >> 2, ec = (lane & 3) * 2;
    #pragma unroll
    for (int mi = 0; mi < 2; mi++) {
        #pragma unroll
        for (int nj = 0; nj < 8; nj++) {
            float* c = acc[mi][nj];
            int m = m0 + wm * 32 + mi * 16 + er;
            int n = n0 + wn * 64 + nj * 8 + ec;
            float b0 = __ldg(bias + n), b1 = __ldg(bias + n + 1);
            if (ID == 0) {
                *(__half2*)(g_h + (size_t)m * 256 + n) =
                    __floats2half2_rn(fmaxf(c[0] + b0, 0.f), fmaxf(c[1] + b1, 0.f));
                *(__half2*)(g_h + (size_t)(m + 8) * 256 + n) =
                    __floats2half2_rn(fmaxf(c[2] + b0, 0.f), fmaxf(c[3] + b1, 0.f));
            } else if (ID == 1) {
                const float* x0 = X + (size_t)m * 256 + n;
                const float* x1 = X + (size_t)(m + 8) * 256 + n;
                *(float2*)(outb + (size_t)m * LDC + n) =
                    make_float2(c[0] + x0[0] + b0, c[1] + x0[1] + b1);
                *(float2*)(outb + (size_t)(m + 8) * LDC + n) =
                    make_float2(c[2] + x1[0] + b0, c[3] + x1[1] + b1);
            } else if (ID == 2) {
                *(float2*)(outb + (size_t)m * LDC + n) = make_float2(c[0] + b0, c[1] + b1);
                *(float2*)(outb + (size_t)(m + 8) * LDC + n) = make_float2(c[2] + b0, c[3] + b1);
            } else {
                float y00 = c[0] + b0, y01 = c[1] + b1;
                float y10 = c[2] + b0, y11 = c[3] + b1;
                *(float2*)(outb + (size_t)m * LDC + n) = make_float2(y00, y01);
                *(float2*)(outb + (size_t)(m + 8) * LDC + n) = make_float2(y10, y11);
                float a0 = y00 + y10, a1 = y01 + y11;
                float q0 = y00 * y00 + y10 * y10, q1 = y01 * y01 + y11 * y11;
                #pragma unroll
                for (int off = 4; off < 32; off <<= 1) {
                    a0 += __shfl_xor_sync(0xffffffffu, a0, off);
                    a1 += __shfl_xor_sync(0xffffffffu, a1, off);
                    q0 += __shfl_xor_sync(0xffffffffu, q0, off);
                    q1 += __shfl_xor_sync(0xffffffffu, q1, off);
                }
                if (er == 0) {
                    atomicAdd(g_S2 + n, a0);
                    atomicAdd(g_S2 + n + 1, a1);
                    atomicAdd(g_Q2 + n, q0);
                    atomicAdd(g_Q2 + n + 1, q1);
                }
            }
        }
    }
}

// ---------------- dual GEMM launch (grid union, heavy spike side first) ----------------
// IDA in {2,3} (spike): linear block -> (by, bz). IDB in {0,1} (mix): -> (bx, by).
template<int IDA, int SA, int IDB, int SB, int NBA>
__global__ void __launch_bounds__(256, 2)
gemm_dual(const uint16_t* __restrict__ BwA, const float* __restrict__ biasA,
          const uint16_t* __restrict__ BwB, const float* __restrict__ biasB,
          const float* __restrict__ XB, float* __restrict__ outB)
{
    extern __shared__ uint8_t smp[];
    int lb = blockIdx.x;
    if (lb < NBA) {
        int by = (IDA == 2) ? (lb & 1) : (lb & 7);
        int bz = (IDA == 2) ? (lb >> 1) : (lb >> 3);
        gemm_core<IDA, SA>(0, by * 128, bz, BwA, biasA, nullptr, nullptr, smp);
    } else {
        int l2 = lb - NBA;
        gemm_core<IDB, SB>((l2 & 1023) * 128, (l2 >> 10) * 128, 0, BwB, biasB, XB, outB, smp);
    }
}

// ---------------- prep union: 4 weight splits + BN2 stat zero ----------------
__device__ __forceinline__ void split_body(const float* src, uint16_t* dst, int n, int i, bool bf, int nbs) {
    if (i >= n) return;
    float v = src[i];
    for (int s = 0; s < nbs; s++) {
        if (bf) {
            __nv_bfloat16 b = __float2bfloat16(v);
            dst[s * n + i] = __bfloat16_as_ushort(b);
            v -= __bfloat162float(b);
        } else {
            __half b = __float2half_rn(v);
            dst[s * n + i] = __half_as_ushort(b);
            v -= __half2float(b);
        }
    }
}
__global__ void prep_union(const float* w1, const float* w2,
                           const float* cw1, const float* cw2) {
    int bx = blockIdx.x, tid = threadIdx.x;
    if (bx < 256)        split_body(w1,  g_w1h,  D_*D_, (bx) * 256 + tid, false, 1);
    else if (bx < 512)   split_body(w2,  g_w2h,  D_*D_, (bx - 256) * 256 + tid, false, 1);
    else if (bx < 1536)  split_body(cw1, g_cw1b, D_*C_, (bx - 512) * 256 + tid, true, 3);
    else if (bx < 2560)  split_body(cw2, g_cw2b, C_*D_, (bx - 1536) * 256 + tid, true, 2);
    else {
        int i = (bx - 2560) * 256 + tid;
        if (i < C_) { g_S2[i] = 0.f; g_Q2[i] = 0.f; }
    }
}

// ---------------- elementwise union: lif1 (long blocks first) + LayerNorm ----------------
__global__ void elem_union(const float* __restrict__ x, const float* __restrict__ gam,
                           const float* __restrict__ bet) {
    if (blockIdx.x < 512) {
        // LIF 1: x[b][c][t] -> s1t[t][b][c] bf16
        int tid = blockIdx.x * 256 + threadIdx.x;
        int b = tid >> 10, c = tid & 1023;
        const float4* xr = (const float4*)(x + ((size_t)b * C_ + c) * D_);
        __nv_bfloat16* sp = g_s1t + (size_t)b * C_ + c;
        float v = 0.0f;
        for (int q = 0; q < 64; q++) {
            float4 xv = xr[q];
            float xa[4] = {xv.x, xv.y, xv.z, xv.w};
            #pragma unroll
            for (int j = 0; j < 4; j++) {
                v = v + (xa[j] - v) * 0.5f;
                float s = (v >= 1.0f) ? 1.0f : 0.0f;
                sp[(size_t)(q * 4 + j) * CB] = __float2bfloat16(s);
                if (v >= 1.0f) v = 0.0f;
            }
        }
    } else {
        // LayerNorm -> fp16 g_xn (1 warp/row)
        int gw = ((blockIdx.x - 512) * 256 + threadIdx.x) >> 5;
        int lane = threadIdx.x & 31;
        const float4* xr = (const float4*)(x + (size_t)gw * D_);
        float4 v0 = xr[lane], v1 = xr[lane + 32];
        float s = v0.x+v0.y+v0.z+v0.w + v1.x+v1.y+v1.z+v1.w;
        float q = v0.x*v0.x+v0.y*v0.y+v0.z*v0.z+v0.w*v0.w + v1.x*v1.x+v1.y*v1.y+v1.z*v1.z+v1.w*v1.w;
        #pragma unroll
        for (int o = 16; o; o >>= 1) {
            s += __shfl_xor_sync(0xffffffffu, s, o);
            q += __shfl_xor_sync(0xffffffffu, q, o);
        }
        float mu = s * (1.0f / D_);
        float rs = rsqrtf(q * (1.0f / D_) - mu * mu + 1e-5f);
        const float4* gg = (const float4*)gam;
        const float4* bb = (const float4*)bet;
        float4 g0 = gg[lane], g1 = gg[lane + 32], b0 = bb[lane], b1 = bb[lane + 32];
        __half2 h0 = __floats2half2_rn((v0.x-mu)*rs*g0.x+b0.x, (v0.y-mu)*rs*g0.y+b0.y);
        __half2 h1 = __floats2half2_rn((v0.z-mu)*rs*g0.z+b0.z, (v0.w-mu)*rs*g0.w+b0.w);
        __half2 h2 = __floats2half2_rn((v1.x-mu)*rs*g1.x+b1.x, (v1.y-mu)*rs*g1.y+b1.y);
        __half2 h3 = __floats2half2_rn((v1.z-mu)*rs*g1.z+b1.z, (v1.w-mu)*rs*g1.w+b1.w);
        __half2* base = (__half2*)(g_xn + (size_t)gw * D_);
        base[2*lane] = h0; base[2*lane+1] = h1;
        base[2*(lane+32)] = h2; base[2*(lane+32)+1] = h3;
    }
}

// ---------------- BN1 two-stage stats (proven, threshold-critical) ----------------
__global__ void bn_slab1() {
    int t = blockIdx.x, tid = threadIdx.x;
    float s = 0.0f, q = 0.0f;
    const float* base = g_y1 + (size_t)t * 128 * 256;
    for (int b = 0; b < 128; b++) {
        float v = base[(size_t)b * 256 + tid];
        s += v; q += v * v;
    }
    g_pS[(size_t)t * 256 + tid] = s;
    g_pQ[(size_t)t * 256 + tid] = q;
}
__global__ void bn_reduce1() {
    int c = blockIdx.x * 256 + threadIdx.x;
    float S = 0.0f, Q = 0.0f;
    for (int t = 0; t < 256; t++) {
        S += g_pS[(size_t)t * 256 + c];
        Q += g_pQ[(size_t)t * 256 + c];
    }
    float mean = S * (1.0f / 32768.0f);
    float var = Q * (1.0f / 32768.0f) - mean * mean;
    g_mu1[c] = mean;
    g_rs1[c] = rsqrtf(var + 1e-5f);
}

// ---------------- BN1 + LIF 2 ----------------
__global__ void lif2_kernel(const float* __restrict__ gam, const float* __restrict__ bet) {
    int tid = blockIdx.x * blockDim.x + threadIdx.x;
    int b = tid >> 8, o = tid & 255;
    float mu = g_mu1[o], rs = g_rs1[o], ga = gam[o], be = bet[o];
    const float* yp = g_y1 + (size_t)b * 256 + o;
    __nv_bfloat16* sp = g_s2t + (size_t)b * 256 + o;
    float v = 0.0f;
    for (int t = 0; t < D_; t++) {
        float yn = ((yp[(size_t)t * 32768] - mu) * rs) * ga + be;
        v = v + (yn - v) * 0.5f;
        float s = (v >= 1.0f) ? 1.0f : 0.0f;
        sp[(size_t)t * 32768] = __float2bfloat16(s);
        if (v >= 1.0f) v = 0.0f;
    }
}

// ---------------- BN2 (inline finalize) + transpose(t,c) + accumulate ----------------
__global__ void final_kernel(float* __restrict__ out, const float* __restrict__ gam,
                             const float* __restrict__ bet) {
    __shared__ float tile[32][33];
    int b = blockIdx.x;
    int c0 = blockIdx.y << 5, t0 = blockIdx.z << 5;
    #pragma unroll
    for (int i = 0; i < 4; i++) {
        int t = t0 + threadIdx.y + i * 8;
        tile[threadIdx.y + i * 8][threadIdx.x] =
            g_y2[(size_t)t * (B_ * 1024) + (size_t)b * 1024 + c0 + threadIdx.x];
    }
    __syncthreads();
    #pragma unroll
    for (int i = 0; i < 4; i++) {
        int c = c0 + threadIdx.y + i * 8;
        float mu = g_S2[c] * (1.0f / 32768.0f);
        float rs = rsqrtf(g_Q2[c] * (1.0f / 32768.0f) - mu * mu + 1e-5f);
        float ga = __ldg(gam + c), be = __ldg(bet + c);
        size_t o = (size_t)b * (C_ * D_) + (size_t)c * D_ + t0 + threadIdx.x;
        out[o] += (tile[threadIdx.x][threadIdx.y + i * 8] - mu) * rs * ga + be;
    }
}

// ---------------- launch ----------------
extern "C" void kernel_launch(void* const* d_in, const int* in_sizes, int n_in,
                              void* d_out, int out_size) {
    const float* x    = (const float*)d_in[0];
    const float* ln_g = (const float*)d_in[1];
    const float* ln_b = (const float*)d_in[2];
    const float* w1   = (const float*)d_in[3];
    const float* b1   = (const float*)d_in[4];
    const float* w2   = (const float*)d_in[5];
    const float* b2   = (const float*)d_in[6];
    const float* cw1  = (const float*)d_in[7];
    const float* cb1  = (const float*)d_in[8];
    const float* bn1g = (const float*)d_in[9];
    const float* bn1b = (const float*)d_in[10];
    const float* cw2  = (const float*)d_in[11];
    const float* cb2  = (const float*)d_in[12];
    const float* bn2g = (const float*)d_in[13];
    const float* bn2b = (const float*)d_in[14];
    float* out = (float*)d_out;
    (void)in_sizes; (void)n_in; (void)out_size;

    uint16_t *dw1h, *dw2h, *dcw1b, *dcw2b;
    cudaGetSymbolAddress((void**)&dw1h, g_w1h);
    cudaGetSymbolAddress((void**)&dw2h, g_w2h);
    cudaGetSymbolAddress((void**)&dcw1b, g_cw1b);
    cudaGetSymbolAddress((void**)&dcw2b, g_cw2b);

    const int smU = 98304;   // uniform 96 KB -> 2 CTAs/SM
    cudaFuncSetAttribute((const void*)gemm_dual<2,3,0,6,512>,
                         cudaFuncAttributeMaxDynamicSharedMemorySize, smU);
    cudaFuncSetAttribute((const void*)gemm_dual<3,4,1,6,2048>,
                         cudaFuncAttributeMaxDynamicSharedMemorySize, smU);

    // prep: weight splits + BN2 stat zero (one launch)
    prep_union<<<2564, 256>>>(w1, w2, cw1, cw2);

    // LIF1 + LayerNorm (one launch; both memory-bound)
    elem_union<<<512 + 16384, 256>>>(x, ln_g, ln_b);

    // U_b: spike GEMM1 (512 heavy CTAs first) ∪ mix GEMM0 (2048 CTAs)
    gemm_dual<2,3,0,6,512><<<2560, 256, smU>>>(dcw1b, cb1, dw1h, b1, nullptr, nullptr);

    // threshold-critical BN1 (proven deterministic path) + LIF2
    bn_slab1<<<256, 256>>>();
    bn_reduce1<<<1, 256>>>();
    lif2_kernel<<<128, 256>>>(bn1g, bn1b);

    // U_c: spike GEMM2 (2048 heavy CTAs first) ∪ mix GEMM1 (2048 CTAs)
    gemm_dual<3,4,1,6,2048><<<4096, 256, smU>>>(dcw2b, cb2, dw2h, b2, x, out);

    // BN2 finalize inline + transpose + accumulate
    final_kernel<<<dim3(B_, C_ / 32, D_ / 32), dim3(32, 8)>>>(out, bn2g, bn2b);
}